// round 1
// baseline (speedup 1.0000x reference)
#include <cuda_runtime.h>
#include <math.h>

#define B_ 4096
#define D_ 512
#define P_ 256
#define C_ 8

// ---------------- scratch (device globals; no allocation allowed) ----------
__device__ float g_tp[P_ * D_];     // tp[p,i] = omega[c_p] @ w[p]
__device__ float g_u[P_ * D_];      // u[p,j]  = omega[c_p]^T @ tp[p]
__device__ float g_p2[P_];          // ||tp_p||^2
__device__ float g_x2[C_ * B_];     // x2[c,b] = ||omega_c x_b||^2  (atomic accum)
__device__ float g_dist[B_ * P_];   // dist[b,p]
__device__ float g_acc[2];          // [0]=sum sigmoid, [1]=sumsq omega

// ---------------------------------------------------------------------------
__global__ void zero_kernel() {
    int i = blockIdx.x * blockDim.x + threadIdx.x;
    if (i < C_ * B_) g_x2[i] = 0.0f;
    if (i < 2) g_acc[i] = 0.0f;
}

// tp[p,i] = sum_j omega[c,i,j] * w[p,j]; prototypes of class c are p_global = 8*pp + c
__global__ __launch_bounds__(256) void tp_kernel(const float* __restrict__ omega,
                                                 const float* __restrict__ protos) {
    int c = blockIdx.y;
    int i0 = blockIdx.x * 32;
    int tid = threadIdx.x;
    int tx = tid & 31;   // local prototype index pp
    int ty = tid >> 5;   // 0..7 -> 4 i's each
    __shared__ float w_s[32][33];
    __shared__ float om_s[32][33];
    float acc[4] = {0.f, 0.f, 0.f, 0.f};
    for (int j0 = 0; j0 < D_; j0 += 32) {
        #pragma unroll
        for (int l = 0; l < 4; l++) {
            int s = tid + l * 256;
            int r = s >> 5, jj = s & 31;
            w_s[r][jj]  = protos[(r * 8 + c) * D_ + j0 + jj];
            om_s[r][jj] = omega[((size_t)c * D_ + i0 + r) * D_ + j0 + jj];
        }
        __syncthreads();
        #pragma unroll
        for (int jj = 0; jj < 32; jj++) {
            float wv = w_s[tx][jj];
            #pragma unroll
            for (int r = 0; r < 4; r++)
                acc[r] += om_s[ty * 4 + r][jj] * wv;
        }
        __syncthreads();
    }
    #pragma unroll
    for (int r = 0; r < 4; r++)
        g_tp[(tx * 8 + c) * D_ + i0 + ty * 4 + r] = acc[r];
}

// u[p,j] = sum_i tp[p,i] * omega[c,i,j]
__global__ __launch_bounds__(256) void u_kernel(const float* __restrict__ omega) {
    int c = blockIdx.y;
    int j0 = blockIdx.x * 64;
    int tid = threadIdx.x;
    int tx = tid & 63;   // j
    int ty = tid >> 6;   // 0..3 -> 8 p's each
    __shared__ float tp_s[32][33];
    __shared__ float om_s[32][65];
    float acc[8];
    #pragma unroll
    for (int r = 0; r < 8; r++) acc[r] = 0.f;
    for (int i0 = 0; i0 < D_; i0 += 32) {
        #pragma unroll
        for (int l = 0; l < 4; l++) {
            int s = tid + l * 256;
            int p = s >> 5, ii = s & 31;
            tp_s[p][ii] = g_tp[(p * 8 + c) * D_ + i0 + ii];
        }
        #pragma unroll
        for (int l = 0; l < 8; l++) {
            int s = tid + l * 256;
            int ii = s >> 6, jj = s & 63;
            om_s[ii][jj] = omega[((size_t)c * D_ + i0 + ii) * D_ + j0 + jj];
        }
        __syncthreads();
        #pragma unroll
        for (int ii = 0; ii < 32; ii++) {
            float ov = om_s[ii][tx];
            #pragma unroll
            for (int r = 0; r < 8; r++)
                acc[r] += tp_s[ty * 8 + r][ii] * ov;
        }
        __syncthreads();
    }
    #pragma unroll
    for (int r = 0; r < 8; r++)
        g_u[((ty * 8 + r) * 8 + c) * D_ + j0 + tx] = acc[r];
}

__global__ void p2_kernel() {
    int p = blockIdx.x;
    int tid = threadIdx.x;
    float s = 0.f;
    for (int i = tid; i < D_; i += 128) {
        float v = g_tp[p * D_ + i];
        s += v * v;
    }
    #pragma unroll
    for (int off = 16; off; off >>= 1) s += __shfl_xor_sync(0xffffffffu, s, off);
    __shared__ float ws[4];
    if ((tid & 31) == 0) ws[tid >> 5] = s;
    __syncthreads();
    if (tid == 0) g_p2[p] = ws[0] + ws[1] + ws[2] + ws[3];
}

// THE big kernel: per class c, Z = X @ omega_c^T, accumulate rowwise sumsq into g_x2[c,b].
// GEMM M=4096 N=512 K=512, NT layout (both operands K-contiguous).
__global__ __launch_bounds__(256) void x2_kernel(const float* __restrict__ X,
                                                 const float* __restrict__ omega) {
    const int BM = 128, BN = 64, BK = 16;
    int c  = blockIdx.z;
    int b0 = blockIdx.x * BM;
    int n0 = blockIdx.y * BN;
    int tid = threadIdx.x;
    int tx = tid & 15;   // n dim (4 cols each)
    int ty = tid >> 4;   // m dim (8 rows each)
    const float* om = omega + (size_t)c * D_ * D_;
    __shared__ float As[BK][BM + 4];
    __shared__ float Bs[BK][BN + 4];
    float acc[8][4];
    #pragma unroll
    for (int i = 0; i < 8; i++)
        #pragma unroll
        for (int j = 0; j < 4; j++) acc[i][j] = 0.f;

    for (int k0 = 0; k0 < D_; k0 += BK) {
        #pragma unroll
        for (int l = 0; l < 2; l++) {
            int s = tid + l * 256;
            int row = s >> 2, kq = s & 3;
            float4 v = *(const float4*)&X[(size_t)(b0 + row) * D_ + k0 + kq * 4];
            As[kq * 4 + 0][row] = v.x;
            As[kq * 4 + 1][row] = v.y;
            As[kq * 4 + 2][row] = v.z;
            As[kq * 4 + 3][row] = v.w;
        }
        {
            int row = tid >> 2, kq = tid & 3;
            float4 v = *(const float4*)&om[(size_t)(n0 + row) * D_ + k0 + kq * 4];
            Bs[kq * 4 + 0][row] = v.x;
            Bs[kq * 4 + 1][row] = v.y;
            Bs[kq * 4 + 2][row] = v.z;
            Bs[kq * 4 + 3][row] = v.w;
        }
        __syncthreads();
        #pragma unroll
        for (int kk = 0; kk < BK; kk++) {
            float4 a0 = *(const float4*)&As[kk][ty * 8];
            float4 a1 = *(const float4*)&As[kk][ty * 8 + 4];
            float4 b  = *(const float4*)&Bs[kk][tx * 4];
            float a[8] = {a0.x, a0.y, a0.z, a0.w, a1.x, a1.y, a1.z, a1.w};
            float bb[4] = {b.x, b.y, b.z, b.w};
            #pragma unroll
            for (int i = 0; i < 8; i++)
                #pragma unroll
                for (int j = 0; j < 4; j++)
                    acc[i][j] += a[i] * bb[j];
        }
        __syncthreads();
    }
    // epilogue: rowwise sum of squares, reduce across the 16 tx lanes
    #pragma unroll
    for (int i = 0; i < 8; i++) {
        float sq = acc[i][0] * acc[i][0] + acc[i][1] * acc[i][1]
                 + acc[i][2] * acc[i][2] + acc[i][3] * acc[i][3];
        #pragma unroll
        for (int off = 1; off < 16; off <<= 1)
            sq += __shfl_xor_sync(0xffffffffu, sq, off);
        if (tx == 0)
            atomicAdd(&g_x2[c * B_ + b0 + ty * 8 + i], sq);
    }
}

// dots GEMM [4096,512]x[512,256] with dist epilogue
__global__ __launch_bounds__(256) void dist_kernel(const float* __restrict__ X,
                                                   const int* __restrict__ labels) {
    const int BM = 128, BN = 64, BK = 16;
    int b0 = blockIdx.x * BM;
    int n0 = blockIdx.y * BN;
    int tid = threadIdx.x;
    int tx = tid & 15;
    int ty = tid >> 4;
    __shared__ float As[BK][BM + 4];
    __shared__ float Bs[BK][BN + 4];
    __shared__ int   lab_s[BN];
    __shared__ float p2_s[BN];
    if (tid < BN) {
        lab_s[tid] = labels[n0 + tid];
        p2_s[tid]  = g_p2[n0 + tid];
    }
    float acc[8][4];
    #pragma unroll
    for (int i = 0; i < 8; i++)
        #pragma unroll
        for (int j = 0; j < 4; j++) acc[i][j] = 0.f;

    for (int k0 = 0; k0 < D_; k0 += BK) {
        #pragma unroll
        for (int l = 0; l < 2; l++) {
            int s = tid + l * 256;
            int row = s >> 2, kq = s & 3;
            float4 v = *(const float4*)&X[(size_t)(b0 + row) * D_ + k0 + kq * 4];
            As[kq * 4 + 0][row] = v.x;
            As[kq * 4 + 1][row] = v.y;
            As[kq * 4 + 2][row] = v.z;
            As[kq * 4 + 3][row] = v.w;
        }
        {
            int row = tid >> 2, kq = tid & 3;
            float4 v = *(const float4*)&g_u[(size_t)(n0 + row) * D_ + k0 + kq * 4];
            Bs[kq * 4 + 0][row] = v.x;
            Bs[kq * 4 + 1][row] = v.y;
            Bs[kq * 4 + 2][row] = v.z;
            Bs[kq * 4 + 3][row] = v.w;
        }
        __syncthreads();
        #pragma unroll
        for (int kk = 0; kk < BK; kk++) {
            float4 a0 = *(const float4*)&As[kk][ty * 8];
            float4 a1 = *(const float4*)&As[kk][ty * 8 + 4];
            float4 b  = *(const float4*)&Bs[kk][tx * 4];
            float a[8] = {a0.x, a0.y, a0.z, a0.w, a1.x, a1.y, a1.z, a1.w};
            float bb[4] = {b.x, b.y, b.z, b.w};
            #pragma unroll
            for (int i = 0; i < 8; i++)
                #pragma unroll
                for (int j = 0; j < 4; j++)
                    acc[i][j] += a[i] * bb[j];
        }
        __syncthreads();
    }
    #pragma unroll
    for (int i = 0; i < 8; i++) {
        int m = b0 + ty * 8 + i;
        float4 o;
        o.x = g_x2[lab_s[tx * 4 + 0] * B_ + m] + p2_s[tx * 4 + 0] - 2.0f * acc[i][0];
        o.y = g_x2[lab_s[tx * 4 + 1] * B_ + m] + p2_s[tx * 4 + 1] - 2.0f * acc[i][1];
        o.z = g_x2[lab_s[tx * 4 + 2] * B_ + m] + p2_s[tx * 4 + 2] - 2.0f * acc[i][2];
        o.w = g_x2[lab_s[tx * 4 + 3] * B_ + m] + p2_s[tx * 4 + 3] - 2.0f * acc[i][3];
        *(float4*)&g_dist[(size_t)m * P_ + n0 + tx * 4] = o;
    }
}

// per-row min pos/neg -> mu -> sigmoid -> sum
__global__ __launch_bounds__(256) void reduce_kernel(const int* __restrict__ y,
                                                     const int* __restrict__ labels) {
    __shared__ int lab_s[P_];
    int tid = threadIdx.x;
    lab_s[tid] = labels[tid];
    __syncthreads();
    int w = tid >> 5, lane = tid & 31;
    int b = blockIdx.x * 8 + w;
    int yv = y[b];
    float pos = INFINITY, neg = INFINITY;
    #pragma unroll
    for (int l = 0; l < 8; l++) {
        int p = lane + l * 32;
        float d = g_dist[(size_t)b * P_ + p];
        if (lab_s[p] == yv) pos = fminf(pos, d);
        else                neg = fminf(neg, d);
    }
    #pragma unroll
    for (int off = 16; off; off >>= 1) {
        pos = fminf(pos, __shfl_xor_sync(0xffffffffu, pos, off));
        neg = fminf(neg, __shfl_xor_sync(0xffffffffu, neg, off));
    }
    __shared__ float part[8];
    if (lane == 0) {
        float mu = (pos - neg) / (pos + neg);
        part[w] = 1.0f / (1.0f + expf(-mu));
    }
    __syncthreads();
    if (tid == 0) {
        float s = 0.f;
        #pragma unroll
        for (int i = 0; i < 8; i++) s += part[i];
        atomicAdd(&g_acc[0], s);
    }
}

__global__ void norm_kernel(const float* __restrict__ omega) {
    float s = 0.f;
    int n = C_ * D_ * D_;
    for (int i = blockIdx.x * blockDim.x + threadIdx.x; i < n; i += gridDim.x * blockDim.x) {
        float v = omega[i];
        s += v * v;
    }
    #pragma unroll
    for (int off = 16; off; off >>= 1) s += __shfl_xor_sync(0xffffffffu, s, off);
    __shared__ float ws[8];
    int lane = threadIdx.x & 31, w = threadIdx.x >> 5;
    if (lane == 0) ws[w] = s;
    __syncthreads();
    if (threadIdx.x == 0) {
        float t = 0.f;
        #pragma unroll
        for (int i = 0; i < 8; i++) t += ws[i];
        atomicAdd(&g_acc[1], t);
    }
}

__global__ void final_kernel(float* out) {
    out[0] = g_acc[0] * (1.0f / (float)B_) + 0.01f * sqrtf(g_acc[1]);
}

extern "C" void kernel_launch(void* const* d_in, const int* in_sizes, int n_in,
                              void* d_out, int out_size) {
    const float* x      = (const float*)d_in[0];
    const int*   y      = (const int*)d_in[1];
    const float* protos = (const float*)d_in[2];
    const float* omega  = (const float*)d_in[3];
    const int*   labels = (const int*)d_in[4];
    float* out = (float*)d_out;

    zero_kernel<<<(C_ * B_ + 255) / 256, 256>>>();
    tp_kernel<<<dim3(D_ / 32, C_), 256>>>(omega, protos);
    p2_kernel<<<P_, 128>>>();
    u_kernel<<<dim3(D_ / 64, C_), 256>>>(omega);
    x2_kernel<<<dim3(B_ / 128, D_ / 64, C_), 256>>>(x, omega);
    dist_kernel<<<dim3(B_ / 128, P_ / 64), 256>>>(x, labels);
    reduce_kernel<<<B_ / 8, 256>>>(y, labels);
    norm_kernel<<<512, 256>>>(omega);
    final_kernel<<<1, 1>>>(out);
}

// round 3
// speedup vs baseline: 3.0069x; 3.0069x over previous
#include <cuda_runtime.h>
#include <math.h>
#include <stdint.h>

#define B_ 4096
#define D_ 512
#define P_ 256
#define C_ 8

// ---------------- scratch (device globals; no allocation allowed) ----------
__device__ __align__(128) float g_tp[P_ * D_];  // tp[p,i] = omega[c_p] @ w[p]
__device__ __align__(128) float g_u[P_ * D_];   // u[p,j]  = omega[c_p]^T @ tp[p]
__device__ float g_p2[P_];                      // ||tp_p||^2
__device__ float g_x2[C_ * B_];                 // x2[c,b] = ||omega_c x_b||^2
__device__ float g_acc[2];                      // [0]=sum sigmoid, [1]=sumsq omega

// ======================= helpers ===========================================
__device__ __forceinline__ uint32_t smem_u32(const void* p) {
    uint32_t a;
    asm("{ .reg .u64 t; cvta.to.shared.u64 t, %1; cvt.u32.u64 %0, t; }"
        : "=r"(a) : "l"(p));
    return a;
}

#define CP_ASYNC16(dst, src) \
    asm volatile("cp.async.cg.shared.global [%0], [%1], 16;" \
                 :: "r"(dst), "l"(src) : "memory")
#define CP_COMMIT() asm volatile("cp.async.commit_group;" ::: "memory")
#define CP_WAIT(n)  asm volatile("cp.async.wait_group %0;" :: "n"(n) : "memory")

// SW128-style swizzle: XOR 16B-group index with row low bits (row stride 128B)
#define SW(b) ((b) ^ (((b) >> 3) & 0x70))

#define MMA_TF32(d, a, b) \
    asm volatile("mma.sync.aligned.m16n8k8.row.col.f32.tf32.tf32.f32 " \
        "{%0,%1,%2,%3}, {%4,%5,%6,%7}, {%8,%9}, {%0,%1,%2,%3};" \
        : "+f"((d)[0]), "+f"((d)[1]), "+f"((d)[2]), "+f"((d)[3]) \
        : "r"((a)[0]), "r"((a)[1]), "r"((a)[2]), "r"((a)[3]), \
          "r"((b)[0]), "r"((b)[1]))

// ===========================================================================
__global__ void zero_kernel() {
    int i = blockIdx.x * blockDim.x + threadIdx.x;
    if (i < C_ * B_) g_x2[i] = 0.0f;
    if (i < 2) g_acc[i] = 0.0f;
}

// tp[p,i] = sum_j omega[c,i,j] * w[p,j]; prototypes of class c are p = 8*pp + c
__global__ __launch_bounds__(256) void tp_kernel(const float* __restrict__ omega,
                                                 const float* __restrict__ protos) {
    int c = blockIdx.y;
    int i0 = blockIdx.x * 32;
    int tid = threadIdx.x;
    int tx = tid & 31;
    int ty = tid >> 5;
    __shared__ float w_s[32][33];
    __shared__ float om_s[32][33];
    float acc[4] = {0.f, 0.f, 0.f, 0.f};
    for (int j0 = 0; j0 < D_; j0 += 32) {
        #pragma unroll
        for (int l = 0; l < 4; l++) {
            int s = tid + l * 256;
            int r = s >> 5, jj = s & 31;
            w_s[r][jj]  = protos[(r * 8 + c) * D_ + j0 + jj];
            om_s[r][jj] = omega[((size_t)c * D_ + i0 + r) * D_ + j0 + jj];
        }
        __syncthreads();
        #pragma unroll
        for (int jj = 0; jj < 32; jj++) {
            float wv = w_s[tx][jj];
            #pragma unroll
            for (int r = 0; r < 4; r++)
                acc[r] += om_s[ty * 4 + r][jj] * wv;
        }
        __syncthreads();
    }
    #pragma unroll
    for (int r = 0; r < 4; r++)
        g_tp[(tx * 8 + c) * D_ + i0 + ty * 4 + r] = acc[r];
}

// u[p,j] = sum_i tp[p,i] * omega[c,i,j]
__global__ __launch_bounds__(256) void u_kernel(const float* __restrict__ omega) {
    int c = blockIdx.y, j0 = blockIdx.x * 32;
    int tid = threadIdx.x;
    int jx = tid & 7;
    int py = tid >> 3;
    __shared__ float tp_s[32][33];
    __shared__ float om_s[32][32];
    float ax = 0.f, ay = 0.f, az = 0.f, aw = 0.f;
    for (int i0 = 0; i0 < D_; i0 += 32) {
        #pragma unroll
        for (int l = 0; l < 4; l++) {
            int s = tid + l * 256;
            int p = s >> 5, ii = s & 31;
            tp_s[p][ii] = g_tp[(p * 8 + c) * D_ + i0 + ii];
        }
        #pragma unroll
        for (int l = 0; l < 4; l++) {
            int s = tid + l * 256;
            int ii = s >> 5, jj = s & 31;
            om_s[ii][jj] = omega[((size_t)c * D_ + i0 + ii) * D_ + j0 + jj];
        }
        __syncthreads();
        #pragma unroll
        for (int ii = 0; ii < 32; ii++) {
            float tv = tp_s[py][ii];
            float4 ov = *(const float4*)&om_s[ii][jx * 4];
            ax += tv * ov.x; ay += tv * ov.y; az += tv * ov.z; aw += tv * ov.w;
        }
        __syncthreads();
    }
    float4 o = {ax, ay, az, aw};
    *(float4*)&g_u[(size_t)(py * 8 + c) * D_ + j0 + jx * 4] = o;
}

__global__ void p2_kernel() {
    int p = blockIdx.x;
    int tid = threadIdx.x;
    float s = 0.f;
    for (int i = tid; i < D_; i += 128) {
        float v = g_tp[p * D_ + i];
        s += v * v;
    }
    #pragma unroll
    for (int off = 16; off; off >>= 1) s += __shfl_xor_sync(0xffffffffu, s, off);
    __shared__ float ws[4];
    if ((tid & 31) == 0) ws[tid >> 5] = s;
    __syncthreads();
    if (tid == 0) g_p2[p] = ws[0] + ws[1] + ws[2] + ws[3];
}

// ================= x2 via mma.sync tf32 (fallback HMMA) ====================
// CTA tile 128(m) x 128(n) x K=512 in BK=32 steps, 8 warps (2m x 4n),
// warp tile 64x32 = 4x4 m16n8k8 tiles. Epilogue: rowwise sumsq -> atomicAdd.
__global__ __launch_bounds__(256) void x2_mma_kernel(const float* __restrict__ X,
                                                     const float* __restrict__ omega) {
    extern __shared__ char sm[];
    const int tid = threadIdx.x, lane = tid & 31, wid = tid >> 5;
    const int warp_m = wid & 1, warp_n = wid >> 1;
    const int b0 = blockIdx.x * 128, n0 = blockIdx.y * 128, c = blockIdx.z;
    const int r4 = lane >> 2, kq4 = lane & 3;

    const float* Asrc = X + (size_t)b0 * D_;
    const float* Bsrc = omega + (size_t)c * D_ * D_ + (size_t)n0 * D_;
    uint32_t smB = smem_u32(sm);

    float acc[4][4][4];
    #pragma unroll
    for (int i = 0; i < 4; i++)
        #pragma unroll
        for (int j = 0; j < 4; j++)
            #pragma unroll
            for (int q = 0; q < 4; q++) acc[i][j][q] = 0.f;

    // frag address bases (byte offsets within a stage)
    uint32_t aRow[4], aXr[4], bRow[4], bXr[4];
    #pragma unroll
    for (int mt = 0; mt < 4; mt++) {
        int row = warp_m * 64 + mt * 16 + r4;
        aRow[mt] = row * 128; aXr[mt] = (row & 7) << 4;
    }
    #pragma unroll
    for (int nt = 0; nt < 4; nt++) {
        int n = warp_n * 32 + nt * 8 + r4;
        bRow[nt] = 16384 + n * 128; bXr[nt] = (n & 7) << 4;
    }

    auto load_stage = [&](int buf, int k0) {
        uint32_t aB = smB + buf * 32768;
        uint32_t bB = aB + 16384;
        #pragma unroll
        for (int l = 0; l < 4; l++) {
            int idx = tid + l * 256;
            int m = idx >> 3, kq = idx & 7;
            uint32_t byteo = m * 128 + kq * 16;
            CP_ASYNC16(aB + SW(byteo), Asrc + (size_t)m * D_ + k0 + kq * 4);
        }
        #pragma unroll
        for (int l = 0; l < 4; l++) {
            int idx = tid + l * 256;
            int n = idx >> 3, kq = idx & 7;
            uint32_t byteo = n * 128 + kq * 16;
            CP_ASYNC16(bB + SW(byteo), Bsrc + (size_t)n * D_ + k0 + kq * 4);
        }
        CP_COMMIT();
    };

    load_stage(0, 0);
    int buf = 0;
    for (int it = 0; it < 16; it++) {
        if (it + 1 < 16) { load_stage(buf ^ 1, (it + 1) * 32); CP_WAIT(1); }
        else             { CP_WAIT(0); }
        __syncthreads();
        uint32_t stage = buf * 32768;
        #pragma unroll
        for (int ks = 0; ks < 4; ks++) {
            uint32_t kb = (ks * 8 + kq4) * 4;
            uint32_t a[4][4], b[4][2];
            #pragma unroll
            for (int mt = 0; mt < 4; mt++) {
                uint32_t base = stage + aRow[mt];
                a[mt][0] = *(const uint32_t*)(sm + base +        (kb        ^ aXr[mt]));
                a[mt][1] = *(const uint32_t*)(sm + base + 1024 + (kb        ^ aXr[mt]));
                a[mt][2] = *(const uint32_t*)(sm + base +        ((kb + 16) ^ aXr[mt]));
                a[mt][3] = *(const uint32_t*)(sm + base + 1024 + ((kb + 16) ^ aXr[mt]));
            }
            #pragma unroll
            for (int nt = 0; nt < 4; nt++) {
                uint32_t base = stage + bRow[nt];
                b[nt][0] = *(const uint32_t*)(sm + base + (kb        ^ bXr[nt]));
                b[nt][1] = *(const uint32_t*)(sm + base + ((kb + 16) ^ bXr[nt]));
            }
            #pragma unroll
            for (int mt = 0; mt < 4; mt++)
                #pragma unroll
                for (int nt = 0; nt < 4; nt++)
                    MMA_TF32(acc[mt][nt], a[mt], b[nt]);
        }
        __syncthreads();
        buf ^= 1;
    }

    // epilogue: rowwise sum of squares over this CTA's 128 n-cols
    #pragma unroll
    for (int mt = 0; mt < 4; mt++) {
        float s0 = 0.f, s8 = 0.f;
        #pragma unroll
        for (int nt = 0; nt < 4; nt++) {
            s0 += acc[mt][nt][0] * acc[mt][nt][0] + acc[mt][nt][1] * acc[mt][nt][1];
            s8 += acc[mt][nt][2] * acc[mt][nt][2] + acc[mt][nt][3] * acc[mt][nt][3];
        }
        s0 += __shfl_xor_sync(0xffffffffu, s0, 1);
        s0 += __shfl_xor_sync(0xffffffffu, s0, 2);
        s8 += __shfl_xor_sync(0xffffffffu, s8, 1);
        s8 += __shfl_xor_sync(0xffffffffu, s8, 2);
        if (kq4 == 0) {
            int row = b0 + warp_m * 64 + mt * 16 + r4;
            atomicAdd(&g_x2[c * B_ + row], s0);
            atomicAdd(&g_x2[c * B_ + row + 8], s8);
        }
    }
}

// ============== dist via mma.sync tf32, fully fused epilogue ===============
// CTA tile 64(m) x 256(n=P) x 512, 8 warps (2m x 4n), warp tile 32x64 =
// 2x8 m16n8k8 tiles. Epilogue: dist -> min pos/neg -> sigmoid -> block sum.
__global__ __launch_bounds__(256) void dist_mma_kernel(const float* __restrict__ X,
                                                       const int* __restrict__ y,
                                                       const int* __restrict__ labels) {
    extern __shared__ char sm[];
    __shared__ float x2s[C_][64];
    __shared__ float p2_s[P_];
    __shared__ int   lab_s[P_];
    __shared__ int   ys_s[64];
    __shared__ float pos_s[4][64];
    __shared__ float neg_s[4][64];
    __shared__ float blk[2];

    const int tid = threadIdx.x, lane = tid & 31, wid = tid >> 5;
    const int warp_m = wid & 1, warp_n = wid >> 1;
    const int b0 = blockIdx.x * 64;
    const int r4 = lane >> 2, kq4 = lane & 3;

    const float* Asrc = X + (size_t)b0 * D_;
    uint32_t smB = smem_u32(sm);

    for (int i = tid; i < P_; i += 256) {
        p2_s[i]  = g_p2[i];
        lab_s[i] = labels[i];
    }
    for (int i = tid; i < C_ * 64; i += 256)
        x2s[i >> 6][i & 63] = g_x2[(i >> 6) * B_ + b0 + (i & 63)];
    if (tid < 64) ys_s[tid] = y[b0 + tid];

    float acc[2][8][4];
    #pragma unroll
    for (int i = 0; i < 2; i++)
        #pragma unroll
        for (int j = 0; j < 8; j++)
            #pragma unroll
            for (int q = 0; q < 4; q++) acc[i][j][q] = 0.f;

    uint32_t aRow[2], aXr[2], bRow[8], bXr[8];
    #pragma unroll
    for (int mt = 0; mt < 2; mt++) {
        int row = warp_m * 32 + mt * 16 + r4;
        aRow[mt] = row * 128; aXr[mt] = (row & 7) << 4;
    }
    #pragma unroll
    for (int nt = 0; nt < 8; nt++) {
        int n = warp_n * 64 + nt * 8 + r4;
        bRow[nt] = 8192 + n * 128; bXr[nt] = (n & 7) << 4;
    }

    auto load_stage = [&](int buf, int k0) {
        uint32_t aB = smB + buf * 40960;
        uint32_t bB = aB + 8192;
        #pragma unroll
        for (int l = 0; l < 2; l++) {
            int idx = tid + l * 256;
            int m = idx >> 3, kq = idx & 7;
            uint32_t byteo = m * 128 + kq * 16;
            CP_ASYNC16(aB + SW(byteo), Asrc + (size_t)m * D_ + k0 + kq * 4);
        }
        #pragma unroll
        for (int l = 0; l < 8; l++) {
            int idx = tid + l * 256;
            int n = idx >> 3, kq = idx & 7;
            uint32_t byteo = n * 128 + kq * 16;
            CP_ASYNC16(bB + SW(byteo), g_u + (size_t)n * D_ + k0 + kq * 4);
        }
        CP_COMMIT();
    };

    load_stage(0, 0);
    int buf = 0;
    for (int it = 0; it < 16; it++) {
        if (it + 1 < 16) { load_stage(buf ^ 1, (it + 1) * 32); CP_WAIT(1); }
        else             { CP_WAIT(0); }
        __syncthreads();
        uint32_t stage = buf * 40960;
        #pragma unroll
        for (int ks = 0; ks < 4; ks++) {
            uint32_t kb = (ks * 8 + kq4) * 4;
            uint32_t a[2][4], b[8][2];
            #pragma unroll
            for (int mt = 0; mt < 2; mt++) {
                uint32_t base = stage + aRow[mt];
                a[mt][0] = *(const uint32_t*)(sm + base +        (kb        ^ aXr[mt]));
                a[mt][1] = *(const uint32_t*)(sm + base + 1024 + (kb        ^ aXr[mt]));
                a[mt][2] = *(const uint32_t*)(sm + base +        ((kb + 16) ^ aXr[mt]));
                a[mt][3] = *(const uint32_t*)(sm + base + 1024 + ((kb + 16) ^ aXr[mt]));
            }
            #pragma unroll
            for (int nt = 0; nt < 8; nt++) {
                uint32_t base = stage + bRow[nt];
                b[nt][0] = *(const uint32_t*)(sm + base + (kb        ^ bXr[nt]));
                b[nt][1] = *(const uint32_t*)(sm + base + ((kb + 16) ^ bXr[nt]));
            }
            #pragma unroll
            for (int mt = 0; mt < 2; mt++)
                #pragma unroll
                for (int nt = 0; nt < 8; nt++)
                    MMA_TF32(acc[mt][nt], a[mt], b[nt]);
        }
        __syncthreads();
        buf ^= 1;
    }

    // ---- fused epilogue ----
    #pragma unroll
    for (int mt = 0; mt < 2; mt++) {
        int rl = warp_m * 32 + mt * 16 + r4;   // local row (and rl+8)
        int y0 = ys_s[rl], y8 = ys_s[rl + 8];
        float p0 = INFINITY, n0v = INFINITY, p8 = INFINITY, n8v = INFINITY;
        #pragma unroll
        for (int nt = 0; nt < 8; nt++) {
            #pragma unroll
            for (int q = 0; q < 2; q++) {
                int p = warp_n * 64 + nt * 8 + kq4 * 2 + q;
                int lb = lab_s[p];
                float pp = p2_s[p];
                float d0 = x2s[lb][rl]     + pp - 2.0f * acc[mt][nt][q];
                float d8 = x2s[lb][rl + 8] + pp - 2.0f * acc[mt][nt][2 + q];
                if (lb == y0) p0 = fminf(p0, d0); else n0v = fminf(n0v, d0);
                if (lb == y8) p8 = fminf(p8, d8); else n8v = fminf(n8v, d8);
            }
        }
        #pragma unroll
        for (int off = 1; off < 4; off <<= 1) {
            p0  = fminf(p0,  __shfl_xor_sync(0xffffffffu, p0,  off));
            n0v = fminf(n0v, __shfl_xor_sync(0xffffffffu, n0v, off));
            p8  = fminf(p8,  __shfl_xor_sync(0xffffffffu, p8,  off));
            n8v = fminf(n8v, __shfl_xor_sync(0xffffffffu, n8v, off));
        }
        if (kq4 == 0) {
            pos_s[warp_n][rl]     = p0;  neg_s[warp_n][rl]     = n0v;
            pos_s[warp_n][rl + 8] = p8;  neg_s[warp_n][rl + 8] = n8v;
        }
    }
    __syncthreads();
    float sg = 0.f;
    if (tid < 64) {
        float pos = fminf(fminf(pos_s[0][tid], pos_s[1][tid]),
                          fminf(pos_s[2][tid], pos_s[3][tid]));
        float neg = fminf(fminf(neg_s[0][tid], neg_s[1][tid]),
                          fminf(neg_s[2][tid], neg_s[3][tid]));
        float mu = (pos - neg) / (pos + neg);
        sg = 1.0f / (1.0f + expf(-mu));
    }
    #pragma unroll
    for (int off = 16; off; off >>= 1) sg += __shfl_xor_sync(0xffffffffu, sg, off);
    if (tid == 0)  blk[0] = sg;
    if (tid == 32) blk[1] = sg;
    __syncthreads();
    if (tid == 0) atomicAdd(&g_acc[0], blk[0] + blk[1]);
}

__global__ void norm_kernel(const float* __restrict__ omega) {
    float s = 0.f;
    int n = C_ * D_ * D_;
    for (int i = blockIdx.x * blockDim.x + threadIdx.x; i < n; i += gridDim.x * blockDim.x) {
        float v = omega[i];
        s += v * v;
    }
    #pragma unroll
    for (int off = 16; off; off >>= 1) s += __shfl_xor_sync(0xffffffffu, s, off);
    __shared__ float ws[8];
    int lane = threadIdx.x & 31, w = threadIdx.x >> 5;
    if (lane == 0) ws[w] = s;
    __syncthreads();
    if (threadIdx.x == 0) {
        float t = 0.f;
        #pragma unroll
        for (int i = 0; i < 8; i++) t += ws[i];
        atomicAdd(&g_acc[1], t);
    }
}

__global__ void final_kernel(float* out) {
    out[0] = g_acc[0] * (1.0f / (float)B_) + 0.01f * sqrtf(g_acc[1]);
}

// ===========================================================================
extern "C" void kernel_launch(void* const* d_in, const int* in_sizes, int n_in,
                              void* d_out, int out_size) {
    const float* x      = (const float*)d_in[0];
    const int*   y      = (const int*)d_in[1];
    const float* protos = (const float*)d_in[2];
    const float* omega  = (const float*)d_in[3];
    const int*   labels = (const int*)d_in[4];
    float* out = (float*)d_out;

    cudaFuncSetAttribute(x2_mma_kernel,  cudaFuncAttributeMaxDynamicSharedMemorySize, 65536);
    cudaFuncSetAttribute(dist_mma_kernel, cudaFuncAttributeMaxDynamicSharedMemorySize, 81920);

    zero_kernel<<<(C_ * B_ + 255) / 256, 256>>>();
    tp_kernel<<<dim3(D_ / 32, C_), 256>>>(omega, protos);
    p2_kernel<<<P_, 128>>>();
    u_kernel<<<dim3(D_ / 32, C_), 256>>>(omega);
    x2_mma_kernel<<<dim3(B_ / 128, 4, C_), 256, 65536>>>(x, omega);
    dist_mma_kernel<<<B_ / 64, 256, 81920>>>(x, y, labels);
    norm_kernel<<<512, 256>>>(omega);
    final_kernel<<<1, 1>>>(out);
}

// round 4
// speedup vs baseline: 3.3270x; 1.1064x over previous
#include <cuda_runtime.h>
#include <math.h>
#include <stdint.h>

#define B_ 4096
#define D_ 512
#define P_ 256
#define C_ 8

// ---------------- scratch (device globals; no allocation allowed) ----------
__device__ __align__(128) float g_tp[P_ * D_];  // tp[p,i] = omega[c_p] @ w[p]
__device__ __align__(128) float g_u[P_ * D_];   // u[p,j]  = omega[c_p]^T @ tp[p]
__device__ float g_p2[P_];                      // ||tp_p||^2
__device__ float g_x2[C_ * B_];                 // x2[c,b] = ||omega_c x_b||^2
__device__ float g_acc[2];                      // [0]=sum sigmoid, [1]=sumsq omega

// ======================= helpers ===========================================
__device__ __forceinline__ uint32_t smem_u32(const void* p) {
    uint32_t a;
    asm("{ .reg .u64 t; cvta.to.shared.u64 t, %1; cvt.u32.u64 %0, t; }"
        : "=r"(a) : "l"(p));
    return a;
}

#define CP_ASYNC16(dst, src) \
    asm volatile("cp.async.cg.shared.global [%0], [%1], 16;" \
                 :: "r"(dst), "l"(src) : "memory")
#define CP_COMMIT() asm volatile("cp.async.commit_group;" ::: "memory")
#define CP_WAIT(n)  asm volatile("cp.async.wait_group %0;" :: "n"(n) : "memory")

// SW128-style swizzle: XOR 16B-group index with row low bits (row stride 128B)
#define SW(b) ((b) ^ (((b) >> 3) & 0x70))

#define MMA_TF32(d, a, b) \
    asm volatile("mma.sync.aligned.m16n8k8.row.col.f32.tf32.tf32.f32 " \
        "{%0,%1,%2,%3}, {%4,%5,%6,%7}, {%8,%9}, {%0,%1,%2,%3};" \
        : "+f"((d)[0]), "+f"((d)[1]), "+f"((d)[2]), "+f"((d)[3]) \
        : "r"((a)[0]), "r"((a)[1]), "r"((a)[2]), "r"((a)[3]), \
          "r"((b)[0]), "r"((b)[1]))

// ===========================================================================
__global__ void zero_kernel() {
    const int n = 2 * P_ * D_ + C_ * B_ + 2;
    for (int i = blockIdx.x * blockDim.x + threadIdx.x; i < n;
         i += gridDim.x * blockDim.x) {
        if (i < P_ * D_)               g_tp[i] = 0.0f;
        else if (i < 2 * P_ * D_)      g_u[i - P_ * D_] = 0.0f;
        else if (i < 2 * P_ * D_ + C_ * B_) g_x2[i - 2 * P_ * D_] = 0.0f;
        else                           g_acc[i - 2 * P_ * D_ - C_ * B_] = 0.0f;
    }
}

// tp[p,i] = sum_j omega[c,i,j] * w[p,j]; split-K x4 via atomicAdd
__global__ __launch_bounds__(256) void tp_kernel(const float* __restrict__ omega,
                                                 const float* __restrict__ protos) {
    int c = blockIdx.y;
    int i0 = blockIdx.x * 32;
    int ks = blockIdx.z;            // K slice: j in [ks*128, ks*128+128)
    int tid = threadIdx.x;
    int tx = tid & 31;
    int ty = tid >> 5;
    __shared__ float w_s[32][33];
    __shared__ float om_s[32][33];
    float acc[4] = {0.f, 0.f, 0.f, 0.f};
    for (int t = 0; t < 4; t++) {
        int j0 = ks * 128 + t * 32;
        #pragma unroll
        for (int l = 0; l < 4; l++) {
            int s = tid + l * 256;
            int r = s >> 5, jj = s & 31;
            w_s[r][jj]  = protos[(r * 8 + c) * D_ + j0 + jj];
            om_s[r][jj] = omega[((size_t)c * D_ + i0 + r) * D_ + j0 + jj];
        }
        __syncthreads();
        #pragma unroll
        for (int jj = 0; jj < 32; jj++) {
            float wv = w_s[tx][jj];
            #pragma unroll
            for (int r = 0; r < 4; r++)
                acc[r] += om_s[ty * 4 + r][jj] * wv;
        }
        __syncthreads();
    }
    #pragma unroll
    for (int r = 0; r < 4; r++)
        atomicAdd(&g_tp[(tx * 8 + c) * D_ + i0 + ty * 4 + r], acc[r]);
}

// u[p,j] = sum_i tp[p,i] * omega[c,i,j]; split-K x4 via atomicAdd
__global__ __launch_bounds__(256) void u_kernel(const float* __restrict__ omega) {
    int c = blockIdx.y, j0 = blockIdx.x * 32;
    int ks = blockIdx.z;            // i in [ks*128, ks*128+128)
    int tid = threadIdx.x;
    int jx = tid & 7;
    int py = tid >> 3;
    __shared__ float tp_s[32][33];
    __shared__ float om_s[32][32];
    float ax = 0.f, ay = 0.f, az = 0.f, aw = 0.f;
    for (int t = 0; t < 4; t++) {
        int i0 = ks * 128 + t * 32;
        #pragma unroll
        for (int l = 0; l < 4; l++) {
            int s = tid + l * 256;
            int p = s >> 5, ii = s & 31;
            tp_s[p][ii] = g_tp[(p * 8 + c) * D_ + i0 + ii];
        }
        #pragma unroll
        for (int l = 0; l < 4; l++) {
            int s = tid + l * 256;
            int ii = s >> 5, jj = s & 31;
            om_s[ii][jj] = omega[((size_t)c * D_ + i0 + ii) * D_ + j0 + jj];
        }
        __syncthreads();
        #pragma unroll
        for (int ii = 0; ii < 32; ii++) {
            float tv = tp_s[py][ii];
            float4 ov = *(const float4*)&om_s[ii][jx * 4];
            ax += tv * ov.x; ay += tv * ov.y; az += tv * ov.z; aw += tv * ov.w;
        }
        __syncthreads();
    }
    float* dst = &g_u[(size_t)(py * 8 + c) * D_ + j0 + jx * 4];
    atomicAdd(dst + 0, ax);
    atomicAdd(dst + 1, ay);
    atomicAdd(dst + 2, az);
    atomicAdd(dst + 3, aw);
}

__global__ void p2_kernel() {
    int p = blockIdx.x;
    int tid = threadIdx.x;
    float s = 0.f;
    for (int i = tid; i < D_; i += 128) {
        float v = g_tp[p * D_ + i];
        s += v * v;
    }
    #pragma unroll
    for (int off = 16; off; off >>= 1) s += __shfl_xor_sync(0xffffffffu, s, off);
    __shared__ float ws[4];
    if ((tid & 31) == 0) ws[tid >> 5] = s;
    __syncthreads();
    if (tid == 0) g_p2[p] = ws[0] + ws[1] + ws[2] + ws[3];
}

// ================= x2 via mma.sync tf32, 3-stage pipeline ==================
// CTA 128m x 128n x K=512 (BK=32), 8 warps (2m x 4n), warp tile 64x32.
__global__ __launch_bounds__(256) void x2_mma_kernel(const float* __restrict__ X,
                                                     const float* __restrict__ omega) {
    extern __shared__ char sm[];
    const int tid = threadIdx.x, lane = tid & 31, wid = tid >> 5;
    const int warp_m = wid & 1, warp_n = wid >> 1;
    const int b0 = blockIdx.x * 128, n0 = blockIdx.y * 128, c = blockIdx.z;
    const int r4 = lane >> 2, kq4 = lane & 3;

    const float* Asrc = X + (size_t)b0 * D_;
    const float* Bsrc = omega + (size_t)c * D_ * D_ + (size_t)n0 * D_;
    uint32_t smB = smem_u32(sm);

    float acc[4][4][4];
    #pragma unroll
    for (int i = 0; i < 4; i++)
        #pragma unroll
        for (int j = 0; j < 4; j++)
            #pragma unroll
            for (int q = 0; q < 4; q++) acc[i][j][q] = 0.f;

    uint32_t aRow[4], aXr[4], bRow[4], bXr[4];
    #pragma unroll
    for (int mt = 0; mt < 4; mt++) {
        int row = warp_m * 64 + mt * 16 + r4;
        aRow[mt] = row * 128; aXr[mt] = (row & 7) << 4;
    }
    #pragma unroll
    for (int nt = 0; nt < 4; nt++) {
        int n = warp_n * 32 + nt * 8 + r4;
        bRow[nt] = 16384 + n * 128; bXr[nt] = (n & 7) << 4;
    }

    auto load_stage = [&](int buf, int k0) {
        uint32_t aB = smB + buf * 32768;
        uint32_t bB = aB + 16384;
        #pragma unroll
        for (int l = 0; l < 4; l++) {
            int idx = tid + l * 256;
            int m = idx >> 3, kq = idx & 7;
            uint32_t byteo = m * 128 + kq * 16;
            CP_ASYNC16(aB + SW(byteo), Asrc + (size_t)m * D_ + k0 + kq * 4);
        }
        #pragma unroll
        for (int l = 0; l < 4; l++) {
            int idx = tid + l * 256;
            int n = idx >> 3, kq = idx & 7;
            uint32_t byteo = n * 128 + kq * 16;
            CP_ASYNC16(bB + SW(byteo), Bsrc + (size_t)n * D_ + k0 + kq * 4);
        }
        CP_COMMIT();
    };

    load_stage(0, 0);
    load_stage(1, 32);
    for (int it = 0; it < 16; it++) {
        if (it == 15) CP_WAIT(0); else CP_WAIT(1);
        __syncthreads();
        if (it + 2 < 16) load_stage((it + 2) % 3, (it + 2) * 32);
        uint32_t stage = (uint32_t)(it % 3) * 32768;
        #pragma unroll
        for (int ks = 0; ks < 4; ks++) {
            uint32_t kb = (ks * 8 + kq4) * 4;
            uint32_t a[4][4], b[4][2];
            #pragma unroll
            for (int mt = 0; mt < 4; mt++) {
                uint32_t base = stage + aRow[mt];
                a[mt][0] = *(const uint32_t*)(sm + base +        (kb        ^ aXr[mt]));
                a[mt][1] = *(const uint32_t*)(sm + base + 1024 + (kb        ^ aXr[mt]));
                a[mt][2] = *(const uint32_t*)(sm + base +        ((kb + 16) ^ aXr[mt]));
                a[mt][3] = *(const uint32_t*)(sm + base + 1024 + ((kb + 16) ^ aXr[mt]));
            }
            #pragma unroll
            for (int nt = 0; nt < 4; nt++) {
                uint32_t base = stage + bRow[nt];
                b[nt][0] = *(const uint32_t*)(sm + base + (kb        ^ bXr[nt]));
                b[nt][1] = *(const uint32_t*)(sm + base + ((kb + 16) ^ bXr[nt]));
            }
            #pragma unroll
            for (int mt = 0; mt < 4; mt++)
                #pragma unroll
                for (int nt = 0; nt < 4; nt++)
                    MMA_TF32(acc[mt][nt], a[mt], b[nt]);
        }
    }

    // epilogue: rowwise sum of squares over this CTA's 128 n-cols
    #pragma unroll
    for (int mt = 0; mt < 4; mt++) {
        float s0 = 0.f, s8 = 0.f;
        #pragma unroll
        for (int nt = 0; nt < 4; nt++) {
            s0 += acc[mt][nt][0] * acc[mt][nt][0] + acc[mt][nt][1] * acc[mt][nt][1];
            s8 += acc[mt][nt][2] * acc[mt][nt][2] + acc[mt][nt][3] * acc[mt][nt][3];
        }
        s0 += __shfl_xor_sync(0xffffffffu, s0, 1);
        s0 += __shfl_xor_sync(0xffffffffu, s0, 2);
        s8 += __shfl_xor_sync(0xffffffffu, s8, 1);
        s8 += __shfl_xor_sync(0xffffffffu, s8, 2);
        if (kq4 == 0) {
            int row = b0 + warp_m * 64 + mt * 16 + r4;
            atomicAdd(&g_x2[c * B_ + row], s0);
            atomicAdd(&g_x2[c * B_ + row + 8], s8);
        }
    }
}

// ============== dist via mma.sync tf32, fully fused epilogue ===============
// CTA 32m x 256n x 512, 8 warps (2m x 4n), warp tile 16x64, 3-stage pipeline.
__global__ __launch_bounds__(256) void dist_mma_kernel(const float* __restrict__ X,
                                                       const int* __restrict__ y,
                                                       const int* __restrict__ labels) {
    extern __shared__ char sm[];
    __shared__ float x2s[C_][32];
    __shared__ float p2_s[P_];
    __shared__ int   lab_s[P_];
    __shared__ int   ys_s[32];
    __shared__ float pos_s[4][32];
    __shared__ float neg_s[4][32];

    const int tid = threadIdx.x, lane = tid & 31, wid = tid >> 5;
    const int warp_m = wid & 1, warp_n = wid >> 1;
    const int b0 = blockIdx.x * 32;
    const int r4 = lane >> 2, kq4 = lane & 3;

    const float* Asrc = X + (size_t)b0 * D_;
    uint32_t smB = smem_u32(sm);

    for (int i = tid; i < P_; i += 256) {
        p2_s[i]  = g_p2[i];
        lab_s[i] = labels[i];
    }
    if (tid < C_ * 32) x2s[tid >> 5][tid & 31] = g_x2[(tid >> 5) * B_ + b0 + (tid & 31)];
    if (tid < 32) ys_s[tid] = y[b0 + tid];

    float acc[8][4];
    #pragma unroll
    for (int j = 0; j < 8; j++)
        #pragma unroll
        for (int q = 0; q < 4; q++) acc[j][q] = 0.f;

    uint32_t aRowB, aXrB, bRow[8], bXr[8];
    {
        int row = warp_m * 16 + r4;
        aRowB = row * 128; aXrB = (row & 7) << 4;
    }
    #pragma unroll
    for (int nt = 0; nt < 8; nt++) {
        int n = warp_n * 64 + nt * 8 + r4;
        bRow[nt] = 4096 + n * 128; bXr[nt] = (n & 7) << 4;
    }

    auto load_stage = [&](int buf, int k0) {
        uint32_t aB = smB + buf * 36864;
        uint32_t bB = aB + 4096;
        {
            int m = tid >> 3, kq = tid & 7;
            uint32_t byteo = m * 128 + kq * 16;
            CP_ASYNC16(aB + SW(byteo), Asrc + (size_t)m * D_ + k0 + kq * 4);
        }
        #pragma unroll
        for (int l = 0; l < 8; l++) {
            int idx = tid + l * 256;
            int n = idx >> 3, kq = idx & 7;
            uint32_t byteo = n * 128 + kq * 16;
            CP_ASYNC16(bB + SW(byteo), g_u + (size_t)n * D_ + k0 + kq * 4);
        }
        CP_COMMIT();
    };

    load_stage(0, 0);
    load_stage(1, 32);
    for (int it = 0; it < 16; it++) {
        if (it == 15) CP_WAIT(0); else CP_WAIT(1);
        __syncthreads();
        if (it + 2 < 16) load_stage((it + 2) % 3, (it + 2) * 32);
        uint32_t stage = (uint32_t)(it % 3) * 36864;
        #pragma unroll
        for (int ks = 0; ks < 4; ks++) {
            uint32_t kb = (ks * 8 + kq4) * 4;
            uint32_t a[4], b[8][2];
            {
                uint32_t base = stage + aRowB;
                a[0] = *(const uint32_t*)(sm + base +        (kb        ^ aXrB));
                a[1] = *(const uint32_t*)(sm + base + 1024 + (kb        ^ aXrB));
                a[2] = *(const uint32_t*)(sm + base +        ((kb + 16) ^ aXrB));
                a[3] = *(const uint32_t*)(sm + base + 1024 + ((kb + 16) ^ aXrB));
            }
            #pragma unroll
            for (int nt = 0; nt < 8; nt++) {
                uint32_t base = stage + bRow[nt];
                b[nt][0] = *(const uint32_t*)(sm + base + (kb        ^ bXr[nt]));
                b[nt][1] = *(const uint32_t*)(sm + base + ((kb + 16) ^ bXr[nt]));
            }
            #pragma unroll
            for (int nt = 0; nt < 8; nt++)
                MMA_TF32(acc[nt], a, b[nt]);
        }
    }

    // ---- fused epilogue ----
    {
        int rl = warp_m * 16 + r4;
        int y0 = ys_s[rl], y8 = ys_s[rl + 8];
        float p0 = INFINITY, n0v = INFINITY, p8 = INFINITY, n8v = INFINITY;
        #pragma unroll
        for (int nt = 0; nt < 8; nt++) {
            #pragma unroll
            for (int q = 0; q < 2; q++) {
                int p = warp_n * 64 + nt * 8 + kq4 * 2 + q;
                int lb = lab_s[p];
                float pp = p2_s[p];
                float d0 = x2s[lb][rl]     + pp - 2.0f * acc[nt][q];
                float d8 = x2s[lb][rl + 8] + pp - 2.0f * acc[nt][2 + q];
                if (lb == y0) p0 = fminf(p0, d0); else n0v = fminf(n0v, d0);
                if (lb == y8) p8 = fminf(p8, d8); else n8v = fminf(n8v, d8);
            }
        }
        #pragma unroll
        for (int off = 1; off < 4; off <<= 1) {
            p0  = fminf(p0,  __shfl_xor_sync(0xffffffffu, p0,  off));
            n0v = fminf(n0v, __shfl_xor_sync(0xffffffffu, n0v, off));
            p8  = fminf(p8,  __shfl_xor_sync(0xffffffffu, p8,  off));
            n8v = fminf(n8v, __shfl_xor_sync(0xffffffffu, n8v, off));
        }
        if (kq4 == 0) {
            pos_s[warp_n][rl]     = p0;  neg_s[warp_n][rl]     = n0v;
            pos_s[warp_n][rl + 8] = p8;  neg_s[warp_n][rl + 8] = n8v;
        }
    }
    __syncthreads();
    if (tid < 32) {
        float pos = fminf(fminf(pos_s[0][tid], pos_s[1][tid]),
                          fminf(pos_s[2][tid], pos_s[3][tid]));
        float neg = fminf(fminf(neg_s[0][tid], neg_s[1][tid]),
                          fminf(neg_s[2][tid], neg_s[3][tid]));
        float mu = (pos - neg) / (pos + neg);
        float sg = 1.0f / (1.0f + expf(-mu));
        #pragma unroll
        for (int off = 16; off; off >>= 1) sg += __shfl_xor_sync(0xffffffffu, sg, off);
        if (tid == 0) atomicAdd(&g_acc[0], sg);
    }
}

__global__ void norm_kernel(const float* __restrict__ omega) {
    float s = 0.f;
    int n = C_ * D_ * D_;
    for (int i = blockIdx.x * blockDim.x + threadIdx.x; i < n; i += gridDim.x * blockDim.x) {
        float v = omega[i];
        s += v * v;
    }
    #pragma unroll
    for (int off = 16; off; off >>= 1) s += __shfl_xor_sync(0xffffffffu, s, off);
    __shared__ float ws[8];
    int lane = threadIdx.x & 31, w = threadIdx.x >> 5;
    if (lane == 0) ws[w] = s;
    __syncthreads();
    if (threadIdx.x == 0) {
        float t = 0.f;
        #pragma unroll
        for (int i = 0; i < 8; i++) t += ws[i];
        atomicAdd(&g_acc[1], t);
    }
}

__global__ void final_kernel(float* out) {
    out[0] = g_acc[0] * (1.0f / (float)B_) + 0.01f * sqrtf(g_acc[1]);
}

// ===========================================================================
extern "C" void kernel_launch(void* const* d_in, const int* in_sizes, int n_in,
                              void* d_out, int out_size) {
    const float* x      = (const float*)d_in[0];
    const int*   y      = (const int*)d_in[1];
    const float* protos = (const float*)d_in[2];
    const float* omega  = (const float*)d_in[3];
    const int*   labels = (const int*)d_in[4];
    float* out = (float*)d_out;

    static cudaStream_t s2 = nullptr;
    static cudaEvent_t evA = nullptr, evB = nullptr;
    if (s2 == nullptr) {                 // first (uncaptured) call only
        cudaStreamCreateWithFlags(&s2, cudaStreamNonBlocking);
        cudaEventCreateWithFlags(&evA, cudaEventDisableTiming);
        cudaEventCreateWithFlags(&evB, cudaEventDisableTiming);
        cudaFuncSetAttribute(x2_mma_kernel,
                             cudaFuncAttributeMaxDynamicSharedMemorySize, 98304);
        cudaFuncSetAttribute(dist_mma_kernel,
                             cudaFuncAttributeMaxDynamicSharedMemorySize, 110592);
    }

    zero_kernel<<<288, 256>>>();
    cudaEventRecord(evA, 0);
    cudaStreamWaitEvent(s2, evA, 0);

    // main stream: the big GEMM immediately
    x2_mma_kernel<<<dim3(B_ / 128, 4, C_), 256, 98304>>>(x, omega);

    // side stream: prototype chain + norm (independent of x2)
    tp_kernel<<<dim3(D_ / 32, C_, 4), 256, 0, s2>>>(omega, protos);
    p2_kernel<<<P_, 128, 0, s2>>>();
    u_kernel<<<dim3(D_ / 32, C_, 4), 256, 0, s2>>>(omega);
    norm_kernel<<<512, 256, 0, s2>>>(omega);
    cudaEventRecord(evB, s2);

    cudaStreamWaitEvent(0, evB, 0);
    dist_mma_kernel<<<B_ / 32, 256, 110592>>>(x, y, labels);
    final_kernel<<<1, 1>>>(out);
}

// round 6
// speedup vs baseline: 4.9330x; 1.4827x over previous
#include <cuda_runtime.h>
#include <cuda_bf16.h>
#include <math.h>
#include <stdint.h>

#define B_ 4096
#define D_ 512
#define P_ 256
#define C_ 8

// ---------------- scratch (device globals; no allocation allowed) ----------
__device__ __align__(128) float g_tp[P_ * D_];  // tp[p,i] = omega[c_p] @ w[p]
__device__ __align__(128) float g_u[P_ * D_];   // u[p,j]  = omega[c_p]^T @ tp[p]
__device__ float g_p2[P_];                      // ||tp_p||^2
__device__ float g_x2[C_ * B_];                 // x2[c,b]
__device__ float g_acc[2];                      // [0]=sum sigmoid, [1]=sumsq omega
__device__ __align__(128) __nv_bfloat16 g_xb[B_ * D_];        // X in bf16
__device__ __align__(128) __nv_bfloat16 g_omb[C_ * D_ * D_];  // omega in bf16
__device__ __align__(128) __nv_bfloat16 g_ub[P_ * D_];        // u in bf16

// ======================= helpers ===========================================
__device__ __forceinline__ uint32_t smem_u32(const void* p) {
    uint32_t a;
    asm("{ .reg .u64 t; cvta.to.shared.u64 t, %1; cvt.u32.u64 %0, t; }"
        : "=r"(a) : "l"(p));
    return a;
}

#define CP_ASYNC16(dst, src) \
    asm volatile("cp.async.cg.shared.global [%0], [%1], 16;" \
                 :: "r"(dst), "l"(src) : "memory")
#define CP_COMMIT() asm volatile("cp.async.commit_group;" ::: "memory")
#define CP_WAIT(n)  asm volatile("cp.async.wait_group %0;" :: "n"(n) : "memory")

// SW128-style swizzle (rows are 128 bytes)
#define SW(b) ((b) ^ (((b) >> 3) & 0x70))

#define MMA_BF16(d, a, b) \
    asm volatile("mma.sync.aligned.m16n8k16.row.col.f32.bf16.bf16.f32 " \
        "{%0,%1,%2,%3}, {%4,%5,%6,%7}, {%8,%9}, {%0,%1,%2,%3};" \
        : "+f"((d)[0]), "+f"((d)[1]), "+f"((d)[2]), "+f"((d)[3]) \
        : "r"((a)[0]), "r"((a)[1]), "r"((a)[2]), "r"((a)[3]), \
          "r"((b)[0]), "r"((b)[1]))

// ===========================================================================
__global__ void zero_kernel() {
    const int n = 2 * P_ * D_ + C_ * B_ + 2;
    for (int i = blockIdx.x * blockDim.x + threadIdx.x; i < n;
         i += gridDim.x * blockDim.x) {
        if (i < P_ * D_)               g_tp[i] = 0.0f;
        else if (i < 2 * P_ * D_)      g_u[i - P_ * D_] = 0.0f;
        else if (i < 2 * P_ * D_ + C_ * B_) g_x2[i - 2 * P_ * D_] = 0.0f;
        else                           g_acc[i - 2 * P_ * D_ - C_ * B_] = 0.0f;
    }
}

// fp32 -> bf16 (4 elems per thread)
__global__ __launch_bounds__(256) void f2bf_kernel(const float* __restrict__ s,
                                                   __nv_bfloat16* __restrict__ d,
                                                   int n4) {
    int i = blockIdx.x * blockDim.x + threadIdx.x;
    if (i < n4) {
        float4 v = ((const float4*)s)[i];
        __nv_bfloat162 lo = __floats2bfloat162_rn(v.x, v.y);
        __nv_bfloat162 hi = __floats2bfloat162_rn(v.z, v.w);
        uint2 o = {*(uint32_t*)&lo, *(uint32_t*)&hi};
        ((uint2*)d)[i] = o;
    }
}

// tp[p,i] = sum_j omega[c,i,j] * w[p,j]; split-K x4 via atomicAdd
__global__ __launch_bounds__(256) void tp_kernel(const float* __restrict__ omega,
                                                 const float* __restrict__ protos) {
    int c = blockIdx.y;
    int i0 = blockIdx.x * 32;
    int ks = blockIdx.z;
    int tid = threadIdx.x;
    int tx = tid & 31;
    int ty = tid >> 5;
    __shared__ float w_s[32][33];
    __shared__ float om_s[32][33];
    float acc[4] = {0.f, 0.f, 0.f, 0.f};
    for (int t = 0; t < 4; t++) {
        int j0 = ks * 128 + t * 32;
        #pragma unroll
        for (int l = 0; l < 4; l++) {
            int s = tid + l * 256;
            int r = s >> 5, jj = s & 31;
            w_s[r][jj]  = protos[(r * 8 + c) * D_ + j0 + jj];
            om_s[r][jj] = omega[((size_t)c * D_ + i0 + r) * D_ + j0 + jj];
        }
        __syncthreads();
        #pragma unroll
        for (int jj = 0; jj < 32; jj++) {
            float wv = w_s[tx][jj];
            #pragma unroll
            for (int r = 0; r < 4; r++)
                acc[r] += om_s[ty * 4 + r][jj] * wv;
        }
        __syncthreads();
    }
    #pragma unroll
    for (int r = 0; r < 4; r++)
        atomicAdd(&g_tp[(tx * 8 + c) * D_ + i0 + ty * 4 + r], acc[r]);
}

// u[p,j] = sum_i tp[p,i] * omega[c,i,j]; split-K x4 via atomicAdd
__global__ __launch_bounds__(256) void u_kernel(const float* __restrict__ omega) {
    int c = blockIdx.y, j0 = blockIdx.x * 32;
    int ks = blockIdx.z;
    int tid = threadIdx.x;
    int jx = tid & 7;
    int py = tid >> 3;
    __shared__ float tp_s[32][33];
    __shared__ float om_s[32][32];
    float ax = 0.f, ay = 0.f, az = 0.f, aw = 0.f;
    for (int t = 0; t < 4; t++) {
        int i0 = ks * 128 + t * 32;
        #pragma unroll
        for (int l = 0; l < 4; l++) {
            int s = tid + l * 256;
            int p = s >> 5, ii = s & 31;
            tp_s[p][ii] = g_tp[(p * 8 + c) * D_ + i0 + ii];
        }
        #pragma unroll
        for (int l = 0; l < 4; l++) {
            int s = tid + l * 256;
            int ii = s >> 5, jj = s & 31;
            om_s[ii][jj] = omega[((size_t)c * D_ + i0 + ii) * D_ + j0 + jj];
        }
        __syncthreads();
        #pragma unroll
        for (int ii = 0; ii < 32; ii++) {
            float tv = tp_s[py][ii];
            float4 ov = *(const float4*)&om_s[ii][jx * 4];
            ax += tv * ov.x; ay += tv * ov.y; az += tv * ov.z; aw += tv * ov.w;
        }
        __syncthreads();
    }
    float* dst = &g_u[(size_t)(py * 8 + c) * D_ + j0 + jx * 4];
    atomicAdd(dst + 0, ax);
    atomicAdd(dst + 1, ay);
    atomicAdd(dst + 2, az);
    atomicAdd(dst + 3, aw);
}

__global__ void p2_kernel() {
    int p = blockIdx.x;
    int tid = threadIdx.x;
    float s = 0.f;
    for (int i = tid; i < D_; i += 128) {
        float v = g_tp[p * D_ + i];
        s += v * v;
    }
    #pragma unroll
    for (int off = 16; off; off >>= 1) s += __shfl_xor_sync(0xffffffffu, s, off);
    __shared__ float ws[4];
    if ((tid & 31) == 0) ws[tid >> 5] = s;
    __syncthreads();
    if (tid == 0) g_p2[p] = ws[0] + ws[1] + ws[2] + ws[3];
}

// ================= x2 via mma.sync bf16 m16n8k16 ===========================
// CTA 128m x 128n x K=512 (BK=64), 8 warps (2m x 4n), warp tile 64x32,
// 3-stage cp.async pipeline. Epilogue: rowwise sumsq -> atomicAdd.
__global__ __launch_bounds__(256) void x2_mma_kernel() {
    extern __shared__ char sm[];
    const int tid = threadIdx.x, lane = tid & 31, wid = tid >> 5;
    const int warp_m = wid & 1, warp_n = wid >> 1;
    const int b0 = blockIdx.x * 128, n0 = blockIdx.y * 128, c = blockIdx.z;
    const int r4 = lane >> 2, kq4 = lane & 3;

    const __nv_bfloat16* Asrc = g_xb + (size_t)b0 * D_;
    const __nv_bfloat16* Bsrc = g_omb + (size_t)c * D_ * D_ + (size_t)n0 * D_;
    uint32_t smB = smem_u32(sm);

    float acc[4][4][4];
    #pragma unroll
    for (int i = 0; i < 4; i++)
        #pragma unroll
        for (int j = 0; j < 4; j++)
            #pragma unroll
            for (int q = 0; q < 4; q++) acc[i][j][q] = 0.f;

    uint32_t aRow[4], aXr[4], bRow[4], bXr[4];
    #pragma unroll
    for (int mt = 0; mt < 4; mt++) {
        int row = warp_m * 64 + mt * 16 + r4;
        aRow[mt] = row * 128; aXr[mt] = (row & 7) << 4;
    }
    #pragma unroll
    for (int nt = 0; nt < 4; nt++) {
        int n = warp_n * 32 + nt * 8 + r4;
        bRow[nt] = 16384 + n * 128; bXr[nt] = (n & 7) << 4;
    }

    // stage = 32KB: A 128x64 bf16 (16KB) + B 128x64 bf16 (16KB)
    auto load_stage = [&](int buf, int k0) {
        uint32_t aB = smB + buf * 32768;
        uint32_t bB = aB + 16384;
        #pragma unroll
        for (int l = 0; l < 4; l++) {
            int idx = tid + l * 256;
            int m = idx >> 3, kq = idx & 7;
            uint32_t byteo = m * 128 + kq * 16;
            CP_ASYNC16(aB + SW(byteo), Asrc + (size_t)m * D_ + k0 + kq * 8);
        }
        #pragma unroll
        for (int l = 0; l < 4; l++) {
            int idx = tid + l * 256;
            int n = idx >> 3, kq = idx & 7;
            uint32_t byteo = n * 128 + kq * 16;
            CP_ASYNC16(bB + SW(byteo), Bsrc + (size_t)n * D_ + k0 + kq * 8);
        }
        CP_COMMIT();
    };

    load_stage(0, 0);
    load_stage(1, 64);
    for (int it = 0; it < 8; it++) {
        if (it == 7) CP_WAIT(0); else CP_WAIT(1);
        __syncthreads();
        if (it + 2 < 8) load_stage((it + 2) % 3, (it + 2) * 64);
        uint32_t stage = (uint32_t)(it % 3) * 32768;
        #pragma unroll
        for (int ks = 0; ks < 4; ks++) {
            uint32_t kb = ks * 32 + kq4 * 4;
            uint32_t a[4][4], b[4][2];
            #pragma unroll
            for (int mt = 0; mt < 4; mt++) {
                uint32_t base = stage + aRow[mt];
                a[mt][0] = *(const uint32_t*)(sm + base +        (kb        ^ aXr[mt]));
                a[mt][1] = *(const uint32_t*)(sm + base + 1024 + (kb        ^ aXr[mt]));
                a[mt][2] = *(const uint32_t*)(sm + base +        ((kb + 16) ^ aXr[mt]));
                a[mt][3] = *(const uint32_t*)(sm + base + 1024 + ((kb + 16) ^ aXr[mt]));
            }
            #pragma unroll
            for (int nt = 0; nt < 4; nt++) {
                uint32_t base = stage + bRow[nt];
                b[nt][0] = *(const uint32_t*)(sm + base + (kb        ^ bXr[nt]));
                b[nt][1] = *(const uint32_t*)(sm + base + ((kb + 16) ^ bXr[nt]));
            }
            #pragma unroll
            for (int mt = 0; mt < 4; mt++)
                #pragma unroll
                for (int nt = 0; nt < 4; nt++)
                    MMA_BF16(acc[mt][nt], a[mt], b[nt]);
        }
    }

    // epilogue: rowwise sum of squares over this CTA's 128 n-cols
    #pragma unroll
    for (int mt = 0; mt < 4; mt++) {
        float s0 = 0.f, s8 = 0.f;
        #pragma unroll
        for (int nt = 0; nt < 4; nt++) {
            s0 += acc[mt][nt][0] * acc[mt][nt][0] + acc[mt][nt][1] * acc[mt][nt][1];
            s8 += acc[mt][nt][2] * acc[mt][nt][2] + acc[mt][nt][3] * acc[mt][nt][3];
        }
        s0 += __shfl_xor_sync(0xffffffffu, s0, 1);
        s0 += __shfl_xor_sync(0xffffffffu, s0, 2);
        s8 += __shfl_xor_sync(0xffffffffu, s8, 1);
        s8 += __shfl_xor_sync(0xffffffffu, s8, 2);
        if (kq4 == 0) {
            int row = b0 + warp_m * 64 + mt * 16 + r4;
            atomicAdd(&g_x2[c * B_ + row], s0);
            atomicAdd(&g_x2[c * B_ + row + 8], s8);
        }
    }
}

// ============== dist via mma.sync bf16, fully fused epilogue ===============
// CTA 32m x 256n x 512 (BK=64), 8 warps (2m x 4n), warp tile 16x64.
__global__ __launch_bounds__(256) void dist_mma_kernel(const int* __restrict__ y,
                                                       const int* __restrict__ labels) {
    extern __shared__ char sm[];
    __shared__ float x2s[C_][32];
    __shared__ float p2_s[P_];
    __shared__ int   lab_s[P_];
    __shared__ int   ys_s[32];
    __shared__ float pos_s[4][32];
    __shared__ float neg_s[4][32];

    const int tid = threadIdx.x, lane = tid & 31, wid = tid >> 5;
    const int warp_m = wid & 1, warp_n = wid >> 1;
    const int b0 = blockIdx.x * 32;
    const int r4 = lane >> 2, kq4 = lane & 3;

    const __nv_bfloat16* Asrc = g_xb + (size_t)b0 * D_;
    uint32_t smB = smem_u32(sm);

    for (int i = tid; i < P_; i += 256) {
        p2_s[i]  = g_p2[i];
        lab_s[i] = labels[i];
    }
    if (tid < C_ * 32) x2s[tid >> 5][tid & 31] = g_x2[(tid >> 5) * B_ + b0 + (tid & 31)];
    if (tid < 32) ys_s[tid] = y[b0 + tid];

    float acc[8][4];
    #pragma unroll
    for (int j = 0; j < 8; j++)
        #pragma unroll
        for (int q = 0; q < 4; q++) acc[j][q] = 0.f;

    uint32_t aRowB, aXrB, bRow[8], bXr[8];
    {
        int row = warp_m * 16 + r4;
        aRowB = row * 128; aXrB = (row & 7) << 4;
    }
    #pragma unroll
    for (int nt = 0; nt < 8; nt++) {
        int n = warp_n * 64 + nt * 8 + r4;
        bRow[nt] = 4096 + n * 128; bXr[nt] = (n & 7) << 4;
    }

    // stage = 36KB: A 32x64 bf16 (4KB) + B 256x64 bf16 (32KB)
    auto load_stage = [&](int buf, int k0) {
        uint32_t aB = smB + buf * 36864;
        uint32_t bB = aB + 4096;
        {
            int m = tid >> 3, kq = tid & 7;
            uint32_t byteo = m * 128 + kq * 16;
            CP_ASYNC16(aB + SW(byteo), Asrc + (size_t)m * D_ + k0 + kq * 8);
        }
        #pragma unroll
        for (int l = 0; l < 8; l++) {
            int idx = tid + l * 256;
            int n = idx >> 3, kq = idx & 7;
            uint32_t byteo = n * 128 + kq * 16;
            CP_ASYNC16(bB + SW(byteo), g_ub + (size_t)n * D_ + k0 + kq * 8);
        }
        CP_COMMIT();
    };

    load_stage(0, 0);
    load_stage(1, 64);
    for (int it = 0; it < 8; it++) {
        if (it == 7) CP_WAIT(0); else CP_WAIT(1);
        __syncthreads();
        if (it + 2 < 8) load_stage((it + 2) % 3, (it + 2) * 64);
        uint32_t stage = (uint32_t)(it % 3) * 36864;
        #pragma unroll
        for (int ks = 0; ks < 4; ks++) {
            uint32_t kb = ks * 32 + kq4 * 4;
            uint32_t a[4], b[8][2];
            {
                uint32_t base = stage + aRowB;
                a[0] = *(const uint32_t*)(sm + base +        (kb        ^ aXrB));
                a[1] = *(const uint32_t*)(sm + base + 1024 + (kb        ^ aXrB));
                a[2] = *(const uint32_t*)(sm + base +        ((kb + 16) ^ aXrB));
                a[3] = *(const uint32_t*)(sm + base + 1024 + ((kb + 16) ^ aXrB));
            }
            #pragma unroll
            for (int nt = 0; nt < 8; nt++) {
                uint32_t base = stage + bRow[nt];
                b[nt][0] = *(const uint32_t*)(sm + base + (kb        ^ bXr[nt]));
                b[nt][1] = *(const uint32_t*)(sm + base + ((kb + 16) ^ bXr[nt]));
            }
            #pragma unroll
            for (int nt = 0; nt < 8; nt++)
                MMA_BF16(acc[nt], a, b[nt]);
        }
    }

    // ---- fused epilogue ----
    {
        int rl = warp_m * 16 + r4;
        int y0 = ys_s[rl], y8 = ys_s[rl + 8];
        float p0 = INFINITY, n0v = INFINITY, p8 = INFINITY, n8v = INFINITY;
        #pragma unroll
        for (int nt = 0; nt < 8; nt++) {
            #pragma unroll
            for (int q = 0; q < 2; q++) {
                int p = warp_n * 64 + nt * 8 + kq4 * 2 + q;
                int lb = lab_s[p];
                float pp = p2_s[p];
                float d0 = x2s[lb][rl]     + pp - 2.0f * acc[nt][q];
                float d8 = x2s[lb][rl + 8] + pp - 2.0f * acc[nt][2 + q];
                if (lb == y0) p0 = fminf(p0, d0); else n0v = fminf(n0v, d0);
                if (lb == y8) p8 = fminf(p8, d8); else n8v = fminf(n8v, d8);
            }
        }
        #pragma unroll
        for (int off = 1; off < 4; off <<= 1) {
            p0  = fminf(p0,  __shfl_xor_sync(0xffffffffu, p0,  off));
            n0v = fminf(n0v, __shfl_xor_sync(0xffffffffu, n0v, off));
            p8  = fminf(p8,  __shfl_xor_sync(0xffffffffu, p8,  off));
            n8v = fminf(n8v, __shfl_xor_sync(0xffffffffu, n8v, off));
        }
        if (kq4 == 0) {
            pos_s[warp_n][rl]     = p0;  neg_s[warp_n][rl]     = n0v;
            pos_s[warp_n][rl + 8] = p8;  neg_s[warp_n][rl + 8] = n8v;
        }
    }
    __syncthreads();
    if (tid < 32) {
        float pos = fminf(fminf(pos_s[0][tid], pos_s[1][tid]),
                          fminf(pos_s[2][tid], pos_s[3][tid]));
        float neg = fminf(fminf(neg_s[0][tid], neg_s[1][tid]),
                          fminf(neg_s[2][tid], neg_s[3][tid]));
        float mu = (pos - neg) / (pos + neg);
        float sg = 1.0f / (1.0f + expf(-mu));
        #pragma unroll
        for (int off = 16; off; off >>= 1) sg += __shfl_xor_sync(0xffffffffu, sg, off);
        if (tid == 0) atomicAdd(&g_acc[0], sg);
    }
}

__global__ void norm_kernel(const float* __restrict__ omega) {
    float s = 0.f;
    int n = C_ * D_ * D_;
    for (int i = blockIdx.x * blockDim.x + threadIdx.x; i < n; i += gridDim.x * blockDim.x) {
        float v = omega[i];
        s += v * v;
    }
    #pragma unroll
    for (int off = 16; off; off >>= 1) s += __shfl_xor_sync(0xffffffffu, s, off);
    __shared__ float ws[8];
    int lane = threadIdx.x & 31, w = threadIdx.x >> 5;
    if (lane == 0) ws[w] = s;
    __syncthreads();
    if (threadIdx.x == 0) {
        float t = 0.f;
        #pragma unroll
        for (int i = 0; i < 8; i++) t += ws[i];
        atomicAdd(&g_acc[1], t);
    }
}

__global__ void final_kernel(float* out) {
    out[0] = g_acc[0] * (1.0f / (float)B_) + 0.01f * sqrtf(g_acc[1]);
}

// ===========================================================================
extern "C" void kernel_launch(void* const* d_in, const int* in_sizes, int n_in,
                              void* d_out, int out_size) {
    const float* x      = (const float*)d_in[0];
    const int*   y      = (const int*)d_in[1];
    const float* protos = (const float*)d_in[2];
    const float* omega  = (const float*)d_in[3];
    const int*   labels = (const int*)d_in[4];
    float* out = (float*)d_out;

    static cudaStream_t s2 = nullptr;
    static cudaEvent_t evA = nullptr, evB = nullptr;
    static __nv_bfloat16* p_xb = nullptr;
    static __nv_bfloat16* p_omb = nullptr;
    static __nv_bfloat16* p_ub = nullptr;
    static float* p_u = nullptr;
    if (s2 == nullptr) {                 // first (uncaptured) call only
        cudaStreamCreateWithFlags(&s2, cudaStreamNonBlocking);
        cudaEventCreateWithFlags(&evA, cudaEventDisableTiming);
        cudaEventCreateWithFlags(&evB, cudaEventDisableTiming);
        cudaFuncSetAttribute(x2_mma_kernel,
                             cudaFuncAttributeMaxDynamicSharedMemorySize, 98304);
        cudaFuncSetAttribute(dist_mma_kernel,
                             cudaFuncAttributeMaxDynamicSharedMemorySize, 110592);
        cudaGetSymbolAddress((void**)&p_xb,  g_xb);
        cudaGetSymbolAddress((void**)&p_omb, g_omb);
        cudaGetSymbolAddress((void**)&p_ub,  g_ub);
        cudaGetSymbolAddress((void**)&p_u,   g_u);
    }

    zero_kernel<<<288, 256>>>();
    cudaEventRecord(evA, 0);
    cudaStreamWaitEvent(s2, evA, 0);

    // main stream: convert inputs, then the big GEMM
    f2bf_kernel<<<(B_ * D_ / 4 + 255) / 256, 256>>>(x, p_xb, B_ * D_ / 4);
    f2bf_kernel<<<(C_ * D_ * D_ / 4 + 255) / 256, 256>>>(omega, p_omb, C_ * D_ * D_ / 4);
    x2_mma_kernel<<<dim3(B_ / 128, 4, C_), 256, 98304>>>();

    // side stream: prototype chain + norm (independent of x2)
    tp_kernel<<<dim3(D_ / 32, C_, 4), 256, 0, s2>>>(omega, protos);
    p2_kernel<<<P_, 128, 0, s2>>>();
    u_kernel<<<dim3(D_ / 32, C_, 4), 256, 0, s2>>>(omega);
    f2bf_kernel<<<(P_ * D_ / 4 + 255) / 256, 256, 0, s2>>>(p_u, p_ub, P_ * D_ / 4);
    norm_kernel<<<512, 256, 0, s2>>>(omega);
    cudaEventRecord(evB, s2);

    cudaStreamWaitEvent(0, evB, 0);
    dist_mma_kernel<<<B_ / 32, 256, 110592>>>(y, labels);
    final_kernel<<<1, 1>>>(out);
}

// round 7
// speedup vs baseline: 5.1463x; 1.0432x over previous
#include <cuda_runtime.h>
#include <cuda_bf16.h>
#include <math.h>
#include <stdint.h>

#define B_ 4096
#define D_ 512
#define P_ 256
#define C_ 8

// ---------------- scratch (device globals; no allocation allowed) ----------
__device__ __align__(128) float g_tp[P_ * D_];  // tp[p,i] = omega[c_p] @ w[p]
__device__ __align__(128) float g_u[P_ * D_];   // u[p,j]  = omega[c_p]^T @ tp[p]
__device__ float g_p2[P_];                      // ||tp_p||^2
__device__ float g_x2[C_ * B_];                 // x2[c,b]
__device__ float g_acc[2];                      // [0]=sum sigmoid, [1]=sumsq omega
__device__ __align__(128) __nv_bfloat16 g_xb[B_ * D_];        // X in bf16
__device__ __align__(128) __nv_bfloat16 g_omb[C_ * D_ * D_];  // omega in bf16
__device__ __align__(128) __nv_bfloat16 g_ub[P_ * D_];        // u in bf16

// ======================= helpers ===========================================
__device__ __forceinline__ uint32_t smem_u32(const void* p) {
    uint32_t a;
    asm("{ .reg .u64 t; cvta.to.shared.u64 t, %1; cvt.u32.u64 %0, t; }"
        : "=r"(a) : "l"(p));
    return a;
}

#define CP_ASYNC16(dst, src) \
    asm volatile("cp.async.cg.shared.global [%0], [%1], 16;" \
                 :: "r"(dst), "l"(src) : "memory")
#define CP_COMMIT() asm volatile("cp.async.commit_group;" ::: "memory")
#define CP_WAIT(n)  asm volatile("cp.async.wait_group %0;" :: "n"(n) : "memory")

// SW128-style swizzle (rows are 128 bytes)
#define SW(b) ((b) ^ (((b) >> 3) & 0x70))

#define MMA_BF16(d, a, b) \
    asm volatile("mma.sync.aligned.m16n8k16.row.col.f32.bf16.bf16.f32 " \
        "{%0,%1,%2,%3}, {%4,%5,%6,%7}, {%8,%9}, {%0,%1,%2,%3};" \
        : "+f"((d)[0]), "+f"((d)[1]), "+f"((d)[2]), "+f"((d)[3]) \
        : "r"((a)[0]), "r"((a)[1]), "r"((a)[2]), "r"((a)[3]), \
          "r"((b)[0]), "r"((b)[1]))

#define LDSM_X4(r, addr) \
    asm volatile("ldmatrix.sync.aligned.m8n8.x4.shared.b16 {%0,%1,%2,%3}, [%4];" \
        : "=r"((r)[0]), "=r"((r)[1]), "=r"((r)[2]), "=r"((r)[3]) : "r"(addr))

// ===========================================================================
__global__ void zero_kernel() {
    const int n = 2 * P_ * D_ + C_ * B_ + 2;
    for (int i = blockIdx.x * blockDim.x + threadIdx.x; i < n;
         i += gridDim.x * blockDim.x) {
        if (i < P_ * D_)               g_tp[i] = 0.0f;
        else if (i < 2 * P_ * D_)      g_u[i - P_ * D_] = 0.0f;
        else if (i < 2 * P_ * D_ + C_ * B_) g_x2[i - 2 * P_ * D_] = 0.0f;
        else                           g_acc[i - 2 * P_ * D_ - C_ * B_] = 0.0f;
    }
}

// fp32 -> bf16 (4 elems per thread)
__global__ __launch_bounds__(256) void f2bf_kernel(const float* __restrict__ s,
                                                   __nv_bfloat16* __restrict__ d,
                                                   int n4) {
    int i = blockIdx.x * blockDim.x + threadIdx.x;
    if (i < n4) {
        float4 v = ((const float4*)s)[i];
        __nv_bfloat162 lo = __floats2bfloat162_rn(v.x, v.y);
        __nv_bfloat162 hi = __floats2bfloat162_rn(v.z, v.w);
        uint2 o = {*(uint32_t*)&lo, *(uint32_t*)&hi};
        ((uint2*)d)[i] = o;
    }
}

// tp[p,i] = sum_j omega[c,i,j] * w[p,j]; split-K x4 via atomicAdd
__global__ __launch_bounds__(256) void tp_kernel(const float* __restrict__ omega,
                                                 const float* __restrict__ protos) {
    int c = blockIdx.y;
    int i0 = blockIdx.x * 32;
    int ks = blockIdx.z;
    int tid = threadIdx.x;
    int tx = tid & 31;
    int ty = tid >> 5;
    __shared__ float w_s[32][33];
    __shared__ float om_s[32][33];
    float acc[4] = {0.f, 0.f, 0.f, 0.f};
    for (int t = 0; t < 4; t++) {
        int j0 = ks * 128 + t * 32;
        #pragma unroll
        for (int l = 0; l < 4; l++) {
            int s = tid + l * 256;
            int r = s >> 5, jj = s & 31;
            w_s[r][jj]  = protos[(r * 8 + c) * D_ + j0 + jj];
            om_s[r][jj] = omega[((size_t)c * D_ + i0 + r) * D_ + j0 + jj];
        }
        __syncthreads();
        #pragma unroll
        for (int jj = 0; jj < 32; jj++) {
            float wv = w_s[tx][jj];
            #pragma unroll
            for (int r = 0; r < 4; r++)
                acc[r] += om_s[ty * 4 + r][jj] * wv;
        }
        __syncthreads();
    }
    #pragma unroll
    for (int r = 0; r < 4; r++)
        atomicAdd(&g_tp[(tx * 8 + c) * D_ + i0 + ty * 4 + r], acc[r]);
}

// u[p,j] = sum_i tp[p,i] * omega[c,i,j]; split-K x4 via atomicAdd
__global__ __launch_bounds__(256) void u_kernel(const float* __restrict__ omega) {
    int c = blockIdx.y, j0 = blockIdx.x * 32;
    int ks = blockIdx.z;
    int tid = threadIdx.x;
    int jx = tid & 7;
    int py = tid >> 3;
    __shared__ float tp_s[32][33];
    __shared__ float om_s[32][32];
    float ax = 0.f, ay = 0.f, az = 0.f, aw = 0.f;
    for (int t = 0; t < 4; t++) {
        int i0 = ks * 128 + t * 32;
        #pragma unroll
        for (int l = 0; l < 4; l++) {
            int s = tid + l * 256;
            int p = s >> 5, ii = s & 31;
            tp_s[p][ii] = g_tp[(p * 8 + c) * D_ + i0 + ii];
        }
        #pragma unroll
        for (int l = 0; l < 4; l++) {
            int s = tid + l * 256;
            int ii = s >> 5, jj = s & 31;
            om_s[ii][jj] = omega[((size_t)c * D_ + i0 + ii) * D_ + j0 + jj];
        }
        __syncthreads();
        #pragma unroll
        for (int ii = 0; ii < 32; ii++) {
            float tv = tp_s[py][ii];
            float4 ov = *(const float4*)&om_s[ii][jx * 4];
            ax += tv * ov.x; ay += tv * ov.y; az += tv * ov.z; aw += tv * ov.w;
        }
        __syncthreads();
    }
    float* dst = &g_u[(size_t)(py * 8 + c) * D_ + j0 + jx * 4];
    atomicAdd(dst + 0, ax);
    atomicAdd(dst + 1, ay);
    atomicAdd(dst + 2, az);
    atomicAdd(dst + 3, aw);
}

__global__ void p2_kernel() {
    int p = blockIdx.x;
    int tid = threadIdx.x;
    float s = 0.f;
    for (int i = tid; i < D_; i += 128) {
        float v = g_tp[p * D_ + i];
        s += v * v;
    }
    #pragma unroll
    for (int off = 16; off; off >>= 1) s += __shfl_xor_sync(0xffffffffu, s, off);
    __shared__ float ws[4];
    if ((tid & 31) == 0) ws[tid >> 5] = s;
    __syncthreads();
    if (tid == 0) g_p2[p] = ws[0] + ws[1] + ws[2] + ws[3];
}

// ================= x2 via mma.sync bf16 + ldmatrix =========================
// CTA 128m x 128n x K=512 (BK=64), 8 warps (2m x 4n), warp tile 64x32,
// 3-stage cp.async pipeline. Epilogue: rowwise sumsq -> atomicAdd.
__global__ __launch_bounds__(256) void x2_mma_kernel() {
    extern __shared__ char sm[];
    const int tid = threadIdx.x, lane = tid & 31, wid = tid >> 5;
    const int warp_m = wid & 1, warp_n = wid >> 1;
    const int b0 = blockIdx.x * 128, n0 = blockIdx.y * 128, c = blockIdx.z;
    const int r4 = lane >> 2, kq4 = lane & 3;

    const __nv_bfloat16* Asrc = g_xb + (size_t)b0 * D_;
    const __nv_bfloat16* Bsrc = g_omb + (size_t)c * D_ * D_ + (size_t)n0 * D_;
    uint32_t smB = smem_u32(sm);

    float acc[4][4][4];
    #pragma unroll
    for (int i = 0; i < 4; i++)
        #pragma unroll
        for (int j = 0; j < 4; j++)
            #pragma unroll
            for (int q = 0; q < 4; q++) acc[i][j][q] = 0.f;

    // ldmatrix per-lane bases
    // A (16x16 per mt): lanes 0-15 -> rows 0-15 khalf0; lanes 16-31 -> khalf1
    uint32_t aBase[4], aX[4];
    const int aRowL = lane & 15, aHalf = (lane >> 4) * 16;
    #pragma unroll
    for (int mt = 0; mt < 4; mt++) {
        int r = warp_m * 64 + mt * 16 + aRowL;
        aBase[mt] = r * 128; aX[mt] = (r & 7) << 4;
    }
    // B (two 8x16 n-tiles per x4): lanes {0-7,8-15,16-23,24-31} ->
    // {ntA k0, ntA k8, ntB k0, ntB k8}
    uint32_t bBase[2], bX[2];
    const int bRowL = ((lane >> 4) << 3) | (lane & 7);
    const int bHalf = ((lane >> 3) & 1) * 16;
    #pragma unroll
    for (int np = 0; np < 2; np++) {
        int r = warp_n * 32 + np * 16 + bRowL;
        bBase[np] = 16384 + r * 128; bX[np] = (r & 7) << 4;
    }

    // stage = 32KB: A 128x64 bf16 (16KB) + B 128x64 bf16 (16KB)
    auto load_stage = [&](int buf, int k0) {
        uint32_t aB = smB + buf * 32768;
        uint32_t bB = aB + 16384;
        #pragma unroll
        for (int l = 0; l < 4; l++) {
            int idx = tid + l * 256;
            int m = idx >> 3, kq = idx & 7;
            uint32_t byteo = m * 128 + kq * 16;
            CP_ASYNC16(aB + SW(byteo), Asrc + (size_t)m * D_ + k0 + kq * 8);
        }
        #pragma unroll
        for (int l = 0; l < 4; l++) {
            int idx = tid + l * 256;
            int n = idx >> 3, kq = idx & 7;
            uint32_t byteo = n * 128 + kq * 16;
            CP_ASYNC16(bB + SW(byteo), Bsrc + (size_t)n * D_ + k0 + kq * 8);
        }
        CP_COMMIT();
    };

    load_stage(0, 0);
    load_stage(1, 64);
    for (int it = 0; it < 8; it++) {
        if (it == 7) CP_WAIT(0); else CP_WAIT(1);
        __syncthreads();
        if (it + 2 < 8) load_stage((it + 2) % 3, (it + 2) * 64);
        uint32_t stage = smB + (uint32_t)(it % 3) * 32768;
        #pragma unroll
        for (int ks = 0; ks < 4; ks++) {
            uint32_t kb = ks * 32;
            uint32_t a[4][4], b[2][4];
            #pragma unroll
            for (int mt = 0; mt < 4; mt++)
                LDSM_X4(a[mt], stage + aBase[mt] + ((kb + aHalf) ^ aX[mt]));
            #pragma unroll
            for (int np = 0; np < 2; np++)
                LDSM_X4(b[np], stage + bBase[np] + ((kb + bHalf) ^ bX[np]));
            #pragma unroll
            for (int mt = 0; mt < 4; mt++)
                #pragma unroll
                for (int nt = 0; nt < 4; nt++)
                    MMA_BF16(acc[mt][nt], a[mt], (&b[nt >> 1][(nt & 1) * 2]));
        }
    }

    // epilogue: rowwise sum of squares over this CTA's 128 n-cols
    #pragma unroll
    for (int mt = 0; mt < 4; mt++) {
        float s0 = 0.f, s8 = 0.f;
        #pragma unroll
        for (int nt = 0; nt < 4; nt++) {
            s0 += acc[mt][nt][0] * acc[mt][nt][0] + acc[mt][nt][1] * acc[mt][nt][1];
            s8 += acc[mt][nt][2] * acc[mt][nt][2] + acc[mt][nt][3] * acc[mt][nt][3];
        }
        s0 += __shfl_xor_sync(0xffffffffu, s0, 1);
        s0 += __shfl_xor_sync(0xffffffffu, s0, 2);
        s8 += __shfl_xor_sync(0xffffffffu, s8, 1);
        s8 += __shfl_xor_sync(0xffffffffu, s8, 2);
        if (kq4 == 0) {
            int row = b0 + warp_m * 64 + mt * 16 + r4;
            atomicAdd(&g_x2[c * B_ + row], s0);
            atomicAdd(&g_x2[c * B_ + row + 8], s8);
        }
    }
}

// ============== dist via mma.sync bf16 + ldmatrix, fused epilogue ==========
// CTA 32m x 256n x 512 (BK=64), 8 warps (2m x 4n), warp tile 16x64.
__global__ __launch_bounds__(256) void dist_mma_kernel(const int* __restrict__ y,
                                                       const int* __restrict__ labels) {
    extern __shared__ char sm[];
    __shared__ float x2s[C_][32];
    __shared__ float p2_s[P_];
    __shared__ int   lab_s[P_];
    __shared__ int   ys_s[32];
    __shared__ float pos_s[4][32];
    __shared__ float neg_s[4][32];

    const int tid = threadIdx.x, lane = tid & 31, wid = tid >> 5;
    const int warp_m = wid & 1, warp_n = wid >> 1;
    const int b0 = blockIdx.x * 32;
    const int r4 = lane >> 2, kq4 = lane & 3;

    const __nv_bfloat16* Asrc = g_xb + (size_t)b0 * D_;
    uint32_t smB = smem_u32(sm);

    for (int i = tid; i < P_; i += 256) {
        p2_s[i]  = g_p2[i];
        lab_s[i] = labels[i];
    }
    if (tid < C_ * 32) x2s[tid >> 5][tid & 31] = g_x2[(tid >> 5) * B_ + b0 + (tid & 31)];
    if (tid < 32) ys_s[tid] = y[b0 + tid];

    float acc[8][4];
    #pragma unroll
    for (int j = 0; j < 8; j++)
        #pragma unroll
        for (int q = 0; q < 4; q++) acc[j][q] = 0.f;

    uint32_t aBase, aX;
    const int aRowL = lane & 15, aHalf = (lane >> 4) * 16;
    {
        int r = warp_m * 16 + aRowL;
        aBase = r * 128; aX = (r & 7) << 4;
    }
    uint32_t bBase[4], bX[4];
    const int bRowL = ((lane >> 4) << 3) | (lane & 7);
    const int bHalf = ((lane >> 3) & 1) * 16;
    #pragma unroll
    for (int np = 0; np < 4; np++) {
        int r = warp_n * 64 + np * 16 + bRowL;
        bBase[np] = 4096 + r * 128; bX[np] = (r & 7) << 4;
    }

    // stage = 36KB: A 32x64 bf16 (4KB) + B 256x64 bf16 (32KB)
    auto load_stage = [&](int buf, int k0) {
        uint32_t aB = smB + buf * 36864;
        uint32_t bB = aB + 4096;
        {
            int m = tid >> 3, kq = tid & 7;
            uint32_t byteo = m * 128 + kq * 16;
            CP_ASYNC16(aB + SW(byteo), Asrc + (size_t)m * D_ + k0 + kq * 8);
        }
        #pragma unroll
        for (int l = 0; l < 8; l++) {
            int idx = tid + l * 256;
            int n = idx >> 3, kq = idx & 7;
            uint32_t byteo = n * 128 + kq * 16;
            CP_ASYNC16(bB + SW(byteo), g_ub + (size_t)n * D_ + k0 + kq * 8);
        }
        CP_COMMIT();
    };

    load_stage(0, 0);
    load_stage(1, 64);
    for (int it = 0; it < 8; it++) {
        if (it == 7) CP_WAIT(0); else CP_WAIT(1);
        __syncthreads();
        if (it + 2 < 8) load_stage((it + 2) % 3, (it + 2) * 64);
        uint32_t stage = smB + (uint32_t)(it % 3) * 36864;
        #pragma unroll
        for (int ks = 0; ks < 4; ks++) {
            uint32_t kb = ks * 32;
            uint32_t a[4], b[4][4];
            LDSM_X4(a, stage + aBase + ((kb + aHalf) ^ aX));
            #pragma unroll
            for (int np = 0; np < 4; np++)
                LDSM_X4(b[np], stage + bBase[np] + ((kb + bHalf) ^ bX[np]));
            #pragma unroll
            for (int nt = 0; nt < 8; nt++)
                MMA_BF16(acc[nt], a, (&b[nt >> 1][(nt & 1) * 2]));
        }
    }

    // ---- fused epilogue ----
    {
        int rl = warp_m * 16 + r4;
        int y0 = ys_s[rl], y8 = ys_s[rl + 8];
        float p0 = INFINITY, n0v = INFINITY, p8 = INFINITY, n8v = INFINITY;
        #pragma unroll
        for (int nt = 0; nt < 8; nt++) {
            #pragma unroll
            for (int q = 0; q < 2; q++) {
                int p = warp_n * 64 + nt * 8 + kq4 * 2 + q;
                int lb = lab_s[p];
                float pp = p2_s[p];
                float d0 = x2s[lb][rl]     + pp - 2.0f * acc[nt][q];
                float d8 = x2s[lb][rl + 8] + pp - 2.0f * acc[nt][2 + q];
                if (lb == y0) p0 = fminf(p0, d0); else n0v = fminf(n0v, d0);
                if (lb == y8) p8 = fminf(p8, d8); else n8v = fminf(n8v, d8);
            }
        }
        #pragma unroll
        for (int off = 1; off < 4; off <<= 1) {
            p0  = fminf(p0,  __shfl_xor_sync(0xffffffffu, p0,  off));
            n0v = fminf(n0v, __shfl_xor_sync(0xffffffffu, n0v, off));
            p8  = fminf(p8,  __shfl_xor_sync(0xffffffffu, p8,  off));
            n8v = fminf(n8v, __shfl_xor_sync(0xffffffffu, n8v, off));
        }
        if (kq4 == 0) {
            pos_s[warp_n][rl]     = p0;  neg_s[warp_n][rl]     = n0v;
            pos_s[warp_n][rl + 8] = p8;  neg_s[warp_n][rl + 8] = n8v;
        }
    }
    __syncthreads();
    if (tid < 32) {
        float pos = fminf(fminf(pos_s[0][tid], pos_s[1][tid]),
                          fminf(pos_s[2][tid], pos_s[3][tid]));
        float neg = fminf(fminf(neg_s[0][tid], neg_s[1][tid]),
                          fminf(neg_s[2][tid], neg_s[3][tid]));
        float mu = (pos - neg) / (pos + neg);
        float sg = 1.0f / (1.0f + expf(-mu));
        #pragma unroll
        for (int off = 16; off; off >>= 1) sg += __shfl_xor_sync(0xffffffffu, sg, off);
        if (tid == 0) atomicAdd(&g_acc[0], sg);
    }
}

__global__ void norm_kernel(const float* __restrict__ omega) {
    float s = 0.f;
    int n = C_ * D_ * D_;
    for (int i = blockIdx.x * blockDim.x + threadIdx.x; i < n; i += gridDim.x * blockDim.x) {
        float v = omega[i];
        s += v * v;
    }
    #pragma unroll
    for (int off = 16; off; off >>= 1) s += __shfl_xor_sync(0xffffffffu, s, off);
    __shared__ float ws[8];
    int lane = threadIdx.x & 31, w = threadIdx.x >> 5;
    if (lane == 0) ws[w] = s;
    __syncthreads();
    if (threadIdx.x == 0) {
        float t = 0.f;
        #pragma unroll
        for (int i = 0; i < 8; i++) t += ws[i];
        atomicAdd(&g_acc[1], t);
    }
}

__global__ void final_kernel(float* out) {
    out[0] = g_acc[0] * (1.0f / (float)B_) + 0.01f * sqrtf(g_acc[1]);
}

// ===========================================================================
extern "C" void kernel_launch(void* const* d_in, const int* in_sizes, int n_in,
                              void* d_out, int out_size) {
    const float* x      = (const float*)d_in[0];
    const int*   y      = (const int*)d_in[1];
    const float* protos = (const float*)d_in[2];
    const float* omega  = (const float*)d_in[3];
    const int*   labels = (const int*)d_in[4];
    float* out = (float*)d_out;

    static cudaStream_t s2 = nullptr;
    static cudaEvent_t evA = nullptr, evB = nullptr;
    static __nv_bfloat16* p_xb = nullptr;
    static __nv_bfloat16* p_omb = nullptr;
    static __nv_bfloat16* p_ub = nullptr;
    static float* p_u = nullptr;
    if (s2 == nullptr) {                 // first (uncaptured) call only
        cudaStreamCreateWithFlags(&s2, cudaStreamNonBlocking);
        cudaEventCreateWithFlags(&evA, cudaEventDisableTiming);
        cudaEventCreateWithFlags(&evB, cudaEventDisableTiming);
        cudaFuncSetAttribute(x2_mma_kernel,
                             cudaFuncAttributeMaxDynamicSharedMemorySize, 98304);
        cudaFuncSetAttribute(dist_mma_kernel,
                             cudaFuncAttributeMaxDynamicSharedMemorySize, 110592);
        cudaGetSymbolAddress((void**)&p_xb,  g_xb);
        cudaGetSymbolAddress((void**)&p_omb, g_omb);
        cudaGetSymbolAddress((void**)&p_ub,  g_ub);
        cudaGetSymbolAddress((void**)&p_u,   g_u);
    }

    zero_kernel<<<288, 256>>>();
    cudaEventRecord(evA, 0);
    cudaStreamWaitEvent(s2, evA, 0);

    // main stream: convert inputs, then the big GEMM
    f2bf_kernel<<<(B_ * D_ / 4 + 255) / 256, 256>>>(x, p_xb, B_ * D_ / 4);
    f2bf_kernel<<<(C_ * D_ * D_ / 4 + 255) / 256, 256>>>(omega, p_omb, C_ * D_ * D_ / 4);
    x2_mma_kernel<<<dim3(B_ / 128, 4, C_), 256, 98304>>>();

    // side stream: prototype chain + norm (independent of x2)
    tp_kernel<<<dim3(D_ / 32, C_, 4), 256, 0, s2>>>(omega, protos);
    p2_kernel<<<P_, 128, 0, s2>>>();
    u_kernel<<<dim3(D_ / 32, C_, 4), 256, 0, s2>>>(omega);
    f2bf_kernel<<<(P_ * D_ / 4 + 255) / 256, 256, 0, s2>>>(p_u, p_ub, P_ * D_ / 4);
    norm_kernel<<<512, 256, 0, s2>>>(omega);
    cudaEventRecord(evB, s2);

    cudaStreamWaitEvent(0, evB, 0);
    dist_mma_kernel<<<B_ / 32, 256, 110592>>>(y, labels);
    final_kernel<<<1, 1>>>(out);
}